// round 13
// baseline (speedup 1.0000x reference)
#include <cuda_runtime.h>
#include <math.h>
#include <stdint.h>

// Problem constants (fixed shapes)
#define BB    512
#define NN    64
#define NFG   1024
#define NFR   256
#define MTOT  (BB * NN)                          // 32768
#define OUT_ELEMS  ((size_t)MTOT * NFG)          // 33554432
#define REL_ELEMS  ((size_t)BB * NN * NN)        // 2097152

// Scratch (device globals — allocation-free)
__device__ float g_tp[(size_t)MTOT * 512];       // theta (cols 0..255) | phi (256..511)
__device__ float g_agg[(size_t)MTOT * NFG];      // relation @ feats (tf32-rounded)
__device__ float g_rel[REL_ELEMS];               // fallback relation scratch
__device__ float g_wtp[(size_t)512 * 1024];      // [N=512][K=1024] = [WthT;WphT], tf32-rounded
__device__ float g_wg[(size_t)1024 * 1024];      // WgT [N][K], tf32-rounded
__device__ float g_bias[512];                    // concat(b_theta, b_phi)

// ---------------------------------------------------------------------------
// Helpers (all compute_80-era PTX or older — legal at compute_103)
// ---------------------------------------------------------------------------
__device__ __forceinline__ uint32_t smem_u32(const void* p) {
    uint32_t a;
    asm("{ .reg .u64 t; cvta.to.shared.u64 t, %1; cvt.u32.u64 %0, t; }" : "=r"(a) : "l"(p));
    return a;
}
__device__ __forceinline__ float rna_tf32(float x) {
    uint32_t r;
    asm("cvt.rna.tf32.f32 %0, %1;" : "=r"(r) : "f"(x));
    return __uint_as_float(r);
}
__device__ __forceinline__ void cp_async16(uint32_t dst, const void* src) {
    asm volatile("cp.async.cg.shared.global [%0], [%1], 16;" :: "r"(dst), "l"(src));
}
#define CP_COMMIT() asm volatile("cp.async.commit_group;" ::: "memory")
#define CP_WAIT1()  asm volatile("cp.async.wait_group 1;" ::: "memory")

__device__ __forceinline__ void ldsm_x4(uint32_t& r0, uint32_t& r1,
                                        uint32_t& r2, uint32_t& r3, uint32_t addr) {
    asm volatile("ldmatrix.sync.aligned.m8n8.x4.shared.b16 {%0,%1,%2,%3}, [%4];"
                 : "=r"(r0), "=r"(r1), "=r"(r2), "=r"(r3) : "r"(addr));
}

__device__ __forceinline__ void mma_tf32(float& d0, float& d1, float& d2, float& d3,
                                         uint32_t a0, uint32_t a1, uint32_t a2, uint32_t a3,
                                         uint32_t b0, uint32_t b1) {
    asm volatile(
        "mma.sync.aligned.m16n8k8.row.col.f32.tf32.tf32.f32 "
        "{%0,%1,%2,%3}, {%4,%5,%6,%7}, {%8,%9}, {%0,%1,%2,%3};"
        : "+f"(d0), "+f"(d1), "+f"(d2), "+f"(d3)
        : "r"(a0), "r"(a1), "r"(a2), "r"(a3), "r"(b0), "r"(b1));
}

// ---------------------------------------------------------------------------
// Fused prologue: all weight transposes (+ tf32 rounding) + bias concat
// in ONE launch. Blocks 0..255: Wth; 256..511: Wph; 512..1535: Wg; 1536: bias.
// ---------------------------------------------------------------------------
__global__ void prep_all_kernel(const float* __restrict__ Wth,
                                const float* __restrict__ Wph,
                                const float* __restrict__ Wg,
                                const float* __restrict__ bth,
                                const float* __restrict__ bph,
                                float* __restrict__ wtp,
                                float* __restrict__ wg,
                                float* __restrict__ bias)
{
    __shared__ float tile[32][33];
    const int b = blockIdx.x;
    const int tx = threadIdx.x, ty = threadIdx.y;   // 32 x 8

    if (b >= 1536) {
        int i = ty * 32 + tx;          // 0..255
        bias[i] = bth[i];
        bias[i + 256] = bph[i];
        return;
    }

    const float* src;
    float* dst;
    int K, N, n0, k0;
    if (b < 256) {
        src = Wth; dst = wtp; K = 1024; N = 256;
        n0 = (b & 7) * 32; k0 = (b >> 3) * 32;
    } else if (b < 512) {
        int t = b - 256;
        src = Wph; dst = wtp + (size_t)256 * 1024; K = 1024; N = 256;
        n0 = (t & 7) * 32; k0 = (t >> 3) * 32;
    } else {
        int t = b - 512;
        src = Wg; dst = wg; K = 1024; N = 1024;
        n0 = (t & 31) * 32; k0 = (t >> 5) * 32;
    }
#pragma unroll
    for (int r = 0; r < 32; r += 8)
        tile[ty + r][tx] = src[(size_t)(k0 + ty + r) * N + n0 + tx];
    __syncthreads();
#pragma unroll
    for (int r = 0; r < 32; r += 8)
        dst[(size_t)(n0 + ty + r) * K + k0 + tx] = rna_tf32(tile[tx][ty + r]);
}

// ---------------------------------------------------------------------------
// tf32 mma.sync GEMM with ldmatrix fragments (R9/R6 configuration — best).
// C[M,N] = op(A[M,K] @ Bt[N,K]^T) (+bias) (relu)
// CTA 128x128, BK=32, 3-stage cp.async, 256 threads (8 warps 2x4,
// warp tile 64x32, 4x4 m16n8k8 per k-step), 2 CTAs/SM.
// Bt pre-rounded to tf32; A consumed raw (HMMA truncation, ~6e-5 rel bias).
// ---------------------------------------------------------------------------
#define STAGE_BYTES 32768u                 // A 16KB + B 16KB
#define GEMM_SMEM   (3 * 32768)            // 98304 bytes -> 2 CTAs/SM

template <int RELU, int HASBIAS>
__global__ void __launch_bounds__(256) gemm_tf32(
    const float* __restrict__ A, int lda,
    const float* __restrict__ Bt, int ldb,
    const float* __restrict__ bias,
    float* __restrict__ C, int ldc, int K)
{
    extern __shared__ float sm[];
    const uint32_t smBase = smem_u32(sm);

    const int tid = threadIdx.x;
    const int bm = blockIdx.y * 128;
    const int bn = blockIdx.x * 128;

    const int wid  = tid >> 5;
    const int lane = tid & 31;
    const int g = lane >> 2;                // MMA groupID
    const int t = lane & 3;                 // MMA threadID_in_group
    const int warp_m = (wid & 1) * 64;
    const int warp_n = (wid >> 1) * 32;

    // ldmatrix per-lane row indices (within 128-row tile)
    const int aRow[4] = {
        warp_m + 0 * 16 + (lane & 7) + ((lane >> 3) & 1) * 8,
        warp_m + 1 * 16 + (lane & 7) + ((lane >> 3) & 1) * 8,
        warp_m + 2 * 16 + (lane & 7) + ((lane >> 3) & 1) * 8,
        warp_m + 3 * 16 + (lane & 7) + ((lane >> 3) & 1) * 8 };
    const int aCsel = lane >> 4;            // 0/1 -> k chunk lo/hi
    const int bRow[2] = {
        warp_n + (0 + ((lane >> 4) & 1)) * 8 + (lane & 7),
        warp_n + (2 + ((lane >> 4) & 1)) * 8 + (lane & 7) };
    const int bCsel = (lane >> 3) & 1;

    // stage one BK=32 chunk into buffer s (8 x cp.async 16B per thread)
    auto stage = [&](int kc, int s) {
        const int k0 = kc * 32;
        const uint32_t base = smBase + (uint32_t)s * STAGE_BYTES;
#pragma unroll
        for (int r = 0; r < 4; ++r) {
            int idx = tid + 256 * r;               // 0..1023
            int row = idx >> 3, c = idx & 7;
            uint32_t dst = base + (uint32_t)(row * 128 + ((c ^ (row & 7)) << 4));
            cp_async16(dst, A + (size_t)(bm + row) * lda + k0 + c * 4);
        }
#pragma unroll
        for (int r = 0; r < 4; ++r) {
            int idx = tid + 256 * r;
            int row = idx >> 3, c = idx & 7;
            uint32_t dst = base + 16384u + (uint32_t)(row * 128 + ((c ^ (row & 7)) << 4));
            cp_async16(dst, Bt + (size_t)(bn + row) * ldb + k0 + c * 4);
        }
    };

    float acc[4][4][4];
#pragma unroll
    for (int mt = 0; mt < 4; ++mt)
#pragma unroll
        for (int nt = 0; nt < 4; ++nt)
#pragma unroll
            for (int q = 0; q < 4; ++q) acc[mt][nt][q] = 0.f;

    const int NC = K / 32;
    stage(0, 0); CP_COMMIT();
    stage(1, 1); CP_COMMIT();

    for (int i = 0; i < NC; ++i) {
        CP_WAIT1();               // this thread's copies of chunk i done
        __syncthreads();          // all threads' copies visible; buf (i+2)%3 free
        if (i + 2 < NC) stage(i + 2, (i + 2) % 3);
        CP_COMMIT();

        const uint32_t sb = smBase + (uint32_t)(i % 3) * STAGE_BYTES;
#pragma unroll
        for (int ks = 0; ks < 4; ++ks) {
            uint32_t a[4][4];
#pragma unroll
            for (int mt = 0; mt < 4; ++mt) {
                const int row = aRow[mt];
                const int c = ks * 2 + aCsel;
                ldsm_x4(a[mt][0], a[mt][1], a[mt][2], a[mt][3],
                        sb + (uint32_t)(row * 128 + ((c ^ (row & 7)) << 4)));
            }
            uint32_t b[4][2];
#pragma unroll
            for (int p = 0; p < 2; ++p) {
                const int row = bRow[p];
                const int c = ks * 2 + bCsel;
                ldsm_x4(b[2 * p][0], b[2 * p][1], b[2 * p + 1][0], b[2 * p + 1][1],
                        sb + 16384u + (uint32_t)(row * 128 + ((c ^ (row & 7)) << 4)));
            }
#pragma unroll
            for (int mt = 0; mt < 4; ++mt)
#pragma unroll
                for (int nt = 0; nt < 4; ++nt)
                    mma_tf32(acc[mt][nt][0], acc[mt][nt][1],
                             acc[mt][nt][2], acc[mt][nt][3],
                             a[mt][0], a[mt][1], a[mt][2], a[mt][3],
                             b[nt][0], b[nt][1]);
        }
    }

    // Epilogue: c0,c1 -> (row, col..col+1); c2,c3 -> (row+8, col..col+1)
#pragma unroll
    for (int mt = 0; mt < 4; ++mt) {
        const int row = bm + warp_m + mt * 16 + g;
#pragma unroll
        for (int nt = 0; nt < 4; ++nt) {
            const int col = bn + warp_n + nt * 8 + 2 * t;
            float v0 = acc[mt][nt][0], v1 = acc[mt][nt][1];
            float v2 = acc[mt][nt][2], v3 = acc[mt][nt][3];
            if (HASBIAS) {
                float b0 = bias[col], b1 = bias[col + 1];
                v0 += b0; v1 += b1; v2 += b0; v3 += b1;
            }
            if (RELU) {
                v0 = fmaxf(v0, 0.f); v1 = fmaxf(v1, 0.f);
                v2 = fmaxf(v2, 0.f); v3 = fmaxf(v3, 0.f);
            }
            *(float2*)(C + (size_t)row * ldc + col) = make_float2(v0, v1);
            *(float2*)(C + (size_t)(row + 8) * ldc + col) = make_float2(v2, v3);
        }
    }
}

// ---------------------------------------------------------------------------
// sim_softmax with tensor-core phase 1 (R12 — unchanged).
// ---------------------------------------------------------------------------
#define SIM_TP    0                        // [128][260] floats (th rows 0..63, ph 64..127)
#define SIM_SS    (128 * 260)              // [64][68]
#define SIM_CX    (SIM_SS + 64 * 68)
#define SIM_CY    (SIM_CX + 64)
#define SIM_SMEM  ((SIM_CY + 64) * 4)      // 151,040 bytes

__global__ void __launch_bounds__(256) sim_softmax_kernel(
    const float* __restrict__ boxes, float* __restrict__ rel)
{
    extern __shared__ float smA[];
    float* sTP = smA + SIM_TP;      // theta rows 0..63, phi rows 64..127, stride 260
    float* sS  = smA + SIM_SS;      // [64][68]
    float* cx  = smA + SIM_CX;
    float* cy  = smA + SIM_CY;

    const int b = blockIdx.x;
    const int tid = threadIdx.x;

    if (tid < 64) {
        const float* bb = boxes + ((size_t)b * 64 + tid) * 4;
        cx[tid] = (bb[0] + bb[2]) * 0.5f;
        cy[tid] = (bb[1] + bb[3]) * 0.5f;
    }

    // Stage theta|phi (RNA-rounded). g_tp row r: 128 float4 (th 0..63, ph 64..127).
    const float4* src4 = (const float4*)(g_tp + (size_t)b * 64 * 512);
    for (int i = tid; i < 64 * 128; i += 256) {
        int r = i >> 7;                // batch row 0..63
        int c4 = i & 127;              // 0..63 theta, 64..127 phi
        float4 v = src4[r * 128 + c4];
        v.x = rna_tf32(v.x); v.y = rna_tf32(v.y);
        v.z = rna_tf32(v.z); v.w = rna_tf32(v.w);
        int row = (c4 < 64) ? r : (64 + r);
        int k4  = (c4 & 63);
        *(float4*)(sTP + row * 260 + k4 * 4) = v;
    }
    __syncthreads();

    // MMA: sim[64,64] = theta @ phi^T. 8 warps: warp_m=(w&1)*32, warp_n=(w>>1)*16.
    const int wid  = tid >> 5;
    const int lane = tid & 31;
    const int g = lane >> 2;
    const int t = lane & 3;
    const int warp_m = (wid & 1) * 32;
    const int warp_n = (wid >> 1) * 16;

    float acc[2][2][4];
#pragma unroll
    for (int mt = 0; mt < 2; ++mt)
#pragma unroll
        for (int nt = 0; nt < 2; ++nt)
#pragma unroll
            for (int q = 0; q < 4; ++q) acc[mt][nt][q] = 0.f;

    const float* sTH = sTP;             // theta rows
    const float* sPH = sTP + 64 * 260;  // phi rows

#pragma unroll 4
    for (int ks = 0; ks < 32; ++ks) {
        const int k0 = ks * 8;
        uint32_t a[2][4];
#pragma unroll
        for (int mt = 0; mt < 2; ++mt) {
            const int r0 = warp_m + mt * 16 + g;
            a[mt][0] = __float_as_uint(sTH[r0 * 260 + k0 + t]);
            a[mt][1] = __float_as_uint(sTH[(r0 + 8) * 260 + k0 + t]);
            a[mt][2] = __float_as_uint(sTH[r0 * 260 + k0 + 4 + t]);
            a[mt][3] = __float_as_uint(sTH[(r0 + 8) * 260 + k0 + 4 + t]);
        }
        uint32_t bf[2][2];
#pragma unroll
        for (int nt = 0; nt < 2; ++nt) {
            const int n = warp_n + nt * 8 + g;
            bf[nt][0] = __float_as_uint(sPH[n * 260 + k0 + t]);
            bf[nt][1] = __float_as_uint(sPH[n * 260 + k0 + 4 + t]);
        }
#pragma unroll
        for (int mt = 0; mt < 2; ++mt)
#pragma unroll
            for (int nt = 0; nt < 2; ++nt)
                mma_tf32(acc[mt][nt][0], acc[mt][nt][1],
                         acc[mt][nt][2], acc[mt][nt][3],
                         a[mt][0], a[mt][1], a[mt][2], a[mt][3],
                         bf[nt][0], bf[nt][1]);
    }

    // write sim/16 into sS
#pragma unroll
    for (int mt = 0; mt < 2; ++mt) {
        const int row = warp_m + mt * 16 + g;
#pragma unroll
        for (int nt = 0; nt < 2; ++nt) {
            const int col = warp_n + nt * 8 + 2 * t;
            sS[row * 68 + col]     = acc[mt][nt][0] * 0.0625f;
            sS[row * 68 + col + 1] = acc[mt][nt][1] * 0.0625f;
            sS[(row + 8) * 68 + col]     = acc[mt][nt][2] * 0.0625f;
            sS[(row + 8) * 68 + col + 1] = acc[mt][nt][3] * 0.0625f;
        }
    }
    __syncthreads();

    // mask + softmax: warp w handles rows 8w..8w+7; lanes cover m (2 each)
    {
        const int w = tid >> 5;
        const int ln = tid & 31;
        const float thr2 = (0.2f * 157.0f) * (0.2f * 157.0f);
#pragma unroll
        for (int r = 0; r < 8; ++r) {
            const int n = w * 8 + r;
            const float cxn = cx[n], cyn = cy[n];
            float dx0 = cxn - cx[ln], dy0 = cyn - cy[ln];
            float dx1 = cxn - cx[ln + 32], dy1 = cyn - cy[ln + 32];
            float v0 = (dx0 * dx0 + dy0 * dy0 > thr2) ? -INFINITY : sS[n * 68 + ln];
            float v1 = (dx1 * dx1 + dy1 * dy1 > thr2) ? -INFINITY : sS[n * 68 + ln + 32];
            float mx = fmaxf(v0, v1);
#pragma unroll
            for (int o = 16; o; o >>= 1)
                mx = fmaxf(mx, __shfl_xor_sync(0xFFFFFFFFu, mx, o));
            float e0 = expf(v0 - mx);
            float e1 = expf(v1 - mx);
            float s = e0 + e1;
#pragma unroll
            for (int o = 16; o; o >>= 1)
                s += __shfl_xor_sync(0xFFFFFFFFu, s, o);
            const float inv = 1.f / s;
            sS[n * 68 + ln] = e0 * inv;
            sS[n * 68 + ln + 32] = e1 * inv;
        }
    }
    __syncthreads();

    float* ro = rel + (size_t)b * 4096;
    for (int i = tid; i < 4096; i += 256)
        ro[i] = sS[(i >> 6) * 68 + (i & 63)];
}

// ---------------------------------------------------------------------------
// agg = relation[64,64] @ feats[64,1024] via tf32 mma.sync.
// RESTRUCTURED for occupancy: CTA = (batch, 128-col chunk), 128 threads
// (4 warps, warp tile 64x32 — unchanged math), smem 52.2KB -> 4 CTAs/SM.
// Grid (512, 8) = 4096 CTAs -> deeper load overlap for the DRAM-bound stream.
// Bank check: sfeats stride 136 == 8 mod 32 -> B banks 8t+g distinct;
// srel stride 68 == 4 mod 32 -> A banks 4g+t distinct.
// Numerics identical to R9/R12 (same RNA points, same k order).
// ---------------------------------------------------------------------------
#define AGG_SMEM ((64 * 136 + 64 * 68) * 4)   // 52224

__global__ void __launch_bounds__(128, 4) agg_kernel(
    const float* __restrict__ feats, const float* __restrict__ rel,
    float* __restrict__ agg)
{
    extern __shared__ float smA[];
    float* sfeats = smA;                 // [64][136]  ([m][f])
    float* srel   = smA + 64 * 136;      // [64][68]   ([n][m])

    const int b = blockIdx.x;
    const int fchunk = blockIdx.y * 128;
    const int tid = threadIdx.x;

    // stage feats chunk (RNA-rounded to tf32): 64 rows x 128 cols = 2048 float4
    const float4* fsrc = (const float4*)(feats + (size_t)b * 64 * 1024 + fchunk);
#pragma unroll
    for (int r = 0; r < 16; ++r) {
        int idx = tid + 128 * r;        // 0..2047
        int m = idx >> 5, c4 = idx & 31;
        float4 v = fsrc[(size_t)m * 256 + c4];
        v.x = rna_tf32(v.x); v.y = rna_tf32(v.y);
        v.z = rna_tf32(v.z); v.w = rna_tf32(v.w);
        *(float4*)(sfeats + m * 136 + c4 * 4) = v;
    }
    // stage rel (RNA-rounded to tf32): 1024 float4
    const float4* rsrc = (const float4*)(rel + (size_t)b * 4096);
#pragma unroll
    for (int r = 0; r < 8; ++r) {
        int idx = tid + 128 * r;        // 0..1023
        int n = idx >> 4, c4 = idx & 15;
        float4 v = rsrc[idx];
        v.x = rna_tf32(v.x); v.y = rna_tf32(v.y);
        v.z = rna_tf32(v.z); v.w = rna_tf32(v.w);
        *(float4*)(srel + n * 68 + c4 * 4) = v;
    }
    __syncthreads();

    const int wid  = tid >> 5;
    const int lane = tid & 31;
    const int g = lane >> 2;
    const int t = lane & 3;
    const int warp_n = wid * 32;         // f-offset within 128 chunk

    float acc[4][4][4];
#pragma unroll
    for (int mt = 0; mt < 4; ++mt)
#pragma unroll
        for (int nt = 0; nt < 4; ++nt)
#pragma unroll
            for (int q = 0; q < 4; ++q) acc[mt][nt][q] = 0.f;

#pragma unroll
    for (int ks = 0; ks < 8; ++ks) {
        const int k0 = ks * 8;
        uint32_t a[4][4];
#pragma unroll
        for (int mt = 0; mt < 4; ++mt) {
            a[mt][0] = __float_as_uint(srel[(mt * 16 + g) * 68 + k0 + t]);
            a[mt][1] = __float_as_uint(srel[(mt * 16 + 8 + g) * 68 + k0 + t]);
            a[mt][2] = __float_as_uint(srel[(mt * 16 + g) * 68 + k0 + 4 + t]);
            a[mt][3] = __float_as_uint(srel[(mt * 16 + 8 + g) * 68 + k0 + 4 + t]);
        }
        uint32_t bf[4][2];
#pragma unroll
        for (int nt = 0; nt < 4; ++nt) {
            bf[nt][0] = __float_as_uint(sfeats[(k0 + t) * 136 + warp_n + nt * 8 + g]);
            bf[nt][1] = __float_as_uint(sfeats[(k0 + 4 + t) * 136 + warp_n + nt * 8 + g]);
        }
#pragma unroll
        for (int mt = 0; mt < 4; ++mt)
#pragma unroll
            for (int nt = 0; nt < 4; ++nt)
                mma_tf32(acc[mt][nt][0], acc[mt][nt][1],
                         acc[mt][nt][2], acc[mt][nt][3],
                         a[mt][0], a[mt][1], a[mt][2], a[mt][3],
                         bf[nt][0], bf[nt][1]);
    }

    // Epilogue: RNA-round for gemm2 consumption
#pragma unroll
    for (int mt = 0; mt < 4; ++mt) {
        const size_t row0 = (size_t)b * 64 + mt * 16 + g;
#pragma unroll
        for (int nt = 0; nt < 4; ++nt) {
            const int col = fchunk + warp_n + nt * 8 + 2 * t;
            float2 p0 = make_float2(rna_tf32(acc[mt][nt][0]), rna_tf32(acc[mt][nt][1]));
            float2 p1 = make_float2(rna_tf32(acc[mt][nt][2]), rna_tf32(acc[mt][nt][3]));
            *(float2*)(agg + row0 * 1024 + col) = p0;
            *(float2*)(agg + (row0 + 8) * 1024 + col) = p1;
        }
    }
}

// ---------------------------------------------------------------------------
extern "C" void kernel_launch(void* const* d_in, const int* in_sizes, int n_in,
                              void* d_out, int out_size)
{
    const float* feats = (const float*)d_in[0];
    const float* boxes = (const float*)d_in[1];
    const float* Wth   = (const float*)d_in[2];
    const float* bth   = (const float*)d_in[3];
    const float* Wph   = (const float*)d_in[4];
    const float* bph   = (const float*)d_in[5];
    const float* Wg    = (const float*)d_in[6];
    float* out = (float*)d_out;

    float *tp, *agg, *relScratch, *wtp, *wg, *bias;
    cudaGetSymbolAddress((void**)&tp, g_tp);
    cudaGetSymbolAddress((void**)&agg, g_agg);
    cudaGetSymbolAddress((void**)&relScratch, g_rel);
    cudaGetSymbolAddress((void**)&wtp, g_wtp);
    cudaGetSymbolAddress((void**)&wg, g_wg);
    cudaGetSymbolAddress((void**)&bias, g_bias);

    cudaFuncSetAttribute(gemm_tf32<0, 1>,
                         cudaFuncAttributeMaxDynamicSharedMemorySize, GEMM_SMEM);
    cudaFuncSetAttribute(gemm_tf32<1, 0>,
                         cudaFuncAttributeMaxDynamicSharedMemorySize, GEMM_SMEM);
    cudaFuncSetAttribute(sim_softmax_kernel,
                         cudaFuncAttributeMaxDynamicSharedMemorySize, SIM_SMEM);
    cudaFuncSetAttribute(agg_kernel,
                         cudaFuncAttributeMaxDynamicSharedMemorySize, AGG_SMEM);

    float* rel = ((size_t)out_size >= OUT_ELEMS + REL_ELEMS)
                     ? out + OUT_ELEMS
                     : relScratch;

    // 5 launches; agg sits in the ncu capture slot (#4).
    prep_all_kernel<<<1537, dim3(32, 8)>>>(Wth, Wph, Wg, bth, bph, wtp, wg, bias); // 1
    gemm_tf32<0, 1><<<dim3(4, 256), 256, GEMM_SMEM>>>(                             // 2
        feats, NFG, wtp, NFG, bias, tp, 512, NFG);
    sim_softmax_kernel<<<BB, 256, SIM_SMEM>>>(boxes, rel);                         // 3
    agg_kernel<<<dim3(BB, 8), 128, AGG_SMEM>>>(feats, rel, agg);                   // 4
    gemm_tf32<1, 0><<<dim3(8, 256), 256, GEMM_SMEM>>>(                             // 5
        agg, NFG, wg, NFG, nullptr, out, NFG, NFG);
}

// round 14
// speedup vs baseline: 1.0816x; 1.0816x over previous
#include <cuda_runtime.h>
#include <math.h>
#include <stdint.h>

// Problem constants (fixed shapes)
#define BB    512
#define NN    64
#define NFG   1024
#define NFR   256
#define MTOT  (BB * NN)                          // 32768
#define OUT_ELEMS  ((size_t)MTOT * NFG)          // 33554432
#define REL_ELEMS  ((size_t)BB * NN * NN)        // 2097152

// Scratch (device globals — allocation-free)
__device__ float g_tp[(size_t)MTOT * 512];       // theta (cols 0..255) | phi (256..511)
__device__ float g_agg[(size_t)MTOT * NFG];      // relation @ feats (tf32-rounded)
__device__ float g_rel[REL_ELEMS];               // fallback relation scratch
__device__ float g_wtp[(size_t)512 * 1024];      // [N=512][K=1024] = [WthT;WphT], tf32-rounded
__device__ float g_wg[(size_t)1024 * 1024];      // WgT [N][K], tf32-rounded
__device__ float g_bias[512];                    // concat(b_theta, b_phi)

// ---------------------------------------------------------------------------
// Helpers (all compute_80-era PTX or older — legal at compute_103)
// ---------------------------------------------------------------------------
__device__ __forceinline__ uint32_t smem_u32(const void* p) {
    uint32_t a;
    asm("{ .reg .u64 t; cvta.to.shared.u64 t, %1; cvt.u32.u64 %0, t; }" : "=r"(a) : "l"(p));
    return a;
}
__device__ __forceinline__ float rna_tf32(float x) {
    uint32_t r;
    asm("cvt.rna.tf32.f32 %0, %1;" : "=r"(r) : "f"(x));
    return __uint_as_float(r);
}
__device__ __forceinline__ void cp_async16(uint32_t dst, const void* src) {
    asm volatile("cp.async.cg.shared.global [%0], [%1], 16;" :: "r"(dst), "l"(src));
}
#define CP_COMMIT() asm volatile("cp.async.commit_group;" ::: "memory")
#define CP_WAIT1()  asm volatile("cp.async.wait_group 1;" ::: "memory")

__device__ __forceinline__ void ldsm_x4(uint32_t& r0, uint32_t& r1,
                                        uint32_t& r2, uint32_t& r3, uint32_t addr) {
    asm volatile("ldmatrix.sync.aligned.m8n8.x4.shared.b16 {%0,%1,%2,%3}, [%4];"
                 : "=r"(r0), "=r"(r1), "=r"(r2), "=r"(r3) : "r"(addr));
}

__device__ __forceinline__ void mma_tf32(float& d0, float& d1, float& d2, float& d3,
                                         uint32_t a0, uint32_t a1, uint32_t a2, uint32_t a3,
                                         uint32_t b0, uint32_t b1) {
    asm volatile(
        "mma.sync.aligned.m16n8k8.row.col.f32.tf32.tf32.f32 "
        "{%0,%1,%2,%3}, {%4,%5,%6,%7}, {%8,%9}, {%0,%1,%2,%3};"
        : "+f"(d0), "+f"(d1), "+f"(d2), "+f"(d3)
        : "r"(a0), "r"(a1), "r"(a2), "r"(a3), "r"(b0), "r"(b1));
}

// ---------------------------------------------------------------------------
// Fused prologue: all weight transposes (+ tf32 rounding) + bias concat
// in ONE launch. Blocks 0..255: Wth; 256..511: Wph; 512..1535: Wg; 1536: bias.
// ---------------------------------------------------------------------------
__global__ void prep_all_kernel(const float* __restrict__ Wth,
                                const float* __restrict__ Wph,
                                const float* __restrict__ Wg,
                                const float* __restrict__ bth,
                                const float* __restrict__ bph,
                                float* __restrict__ wtp,
                                float* __restrict__ wg,
                                float* __restrict__ bias)
{
    __shared__ float tile[32][33];
    const int b = blockIdx.x;
    const int tx = threadIdx.x, ty = threadIdx.y;   // 32 x 8

    if (b >= 1536) {
        int i = ty * 32 + tx;          // 0..255
        bias[i] = bth[i];
        bias[i + 256] = bph[i];
        return;
    }

    const float* src;
    float* dst;
    int K, N, n0, k0;
    if (b < 256) {
        src = Wth; dst = wtp; K = 1024; N = 256;
        n0 = (b & 7) * 32; k0 = (b >> 3) * 32;
    } else if (b < 512) {
        int t = b - 256;
        src = Wph; dst = wtp + (size_t)256 * 1024; K = 1024; N = 256;
        n0 = (t & 7) * 32; k0 = (t >> 3) * 32;
    } else {
        int t = b - 512;
        src = Wg; dst = wg; K = 1024; N = 1024;
        n0 = (t & 31) * 32; k0 = (t >> 5) * 32;
    }
#pragma unroll
    for (int r = 0; r < 32; r += 8)
        tile[ty + r][tx] = src[(size_t)(k0 + ty + r) * N + n0 + tx];
    __syncthreads();
#pragma unroll
    for (int r = 0; r < 32; r += 8)
        dst[(size_t)(n0 + ty + r) * K + k0 + tx] = rna_tf32(tile[tx][ty + r]);
}

// ---------------------------------------------------------------------------
// tf32 mma.sync GEMM with ldmatrix fragments (R9/R6 configuration — best).
// C[M,N] = op(A[M,K] @ Bt[N,K]^T) (+bias) (relu). K compile-time (1024).
// CTA 128x128, BK=32, 3-stage cp.async, 256 threads (8 warps 2x4,
// warp tile 64x32, 4x4 m16n8k8 per k-step), 2 CTAs/SM.
// Bt pre-rounded to tf32; A consumed raw (HMMA truncation, ~6e-5 rel bias).
// ---------------------------------------------------------------------------
#define STAGE_BYTES 32768u                 // A 16KB + B 16KB
#define GEMM_SMEM   (3 * 32768)            // 98304 bytes -> 2 CTAs/SM

template <int RELU, int HASBIAS, int K>
__global__ void __launch_bounds__(256) gemm_tf32(
    const float* __restrict__ A, int lda,
    const float* __restrict__ Bt, int ldb,
    const float* __restrict__ bias,
    float* __restrict__ C, int ldc)
{
    extern __shared__ float sm[];
    const uint32_t smBase = smem_u32(sm);

    const int tid = threadIdx.x;
    const int bm = blockIdx.y * 128;
    const int bn = blockIdx.x * 128;

    const int wid  = tid >> 5;
    const int lane = tid & 31;
    const int g = lane >> 2;                // MMA groupID
    const int t = lane & 3;                 // MMA threadID_in_group
    const int warp_m = (wid & 1) * 64;
    const int warp_n = (wid >> 1) * 32;

    // ldmatrix per-lane row indices (within 128-row tile)
    const int aRow[4] = {
        warp_m + 0 * 16 + (lane & 7) + ((lane >> 3) & 1) * 8,
        warp_m + 1 * 16 + (lane & 7) + ((lane >> 3) & 1) * 8,
        warp_m + 2 * 16 + (lane & 7) + ((lane >> 3) & 1) * 8,
        warp_m + 3 * 16 + (lane & 7) + ((lane >> 3) & 1) * 8 };
    const int aCsel = lane >> 4;            // 0/1 -> k chunk lo/hi
    const int bRow[2] = {
        warp_n + (0 + ((lane >> 4) & 1)) * 8 + (lane & 7),
        warp_n + (2 + ((lane >> 4) & 1)) * 8 + (lane & 7) };
    const int bCsel = (lane >> 3) & 1;

    // stage one BK=32 chunk into buffer s (8 x cp.async 16B per thread)
    auto stage = [&](int kc, int s) {
        const int k0 = kc * 32;
        const uint32_t base = smBase + (uint32_t)s * STAGE_BYTES;
#pragma unroll
        for (int r = 0; r < 4; ++r) {
            int idx = tid + 256 * r;               // 0..1023
            int row = idx >> 3, c = idx & 7;
            uint32_t dst = base + (uint32_t)(row * 128 + ((c ^ (row & 7)) << 4));
            cp_async16(dst, A + (size_t)(bm + row) * lda + k0 + c * 4);
        }
#pragma unroll
        for (int r = 0; r < 4; ++r) {
            int idx = tid + 256 * r;
            int row = idx >> 3, c = idx & 7;
            uint32_t dst = base + 16384u + (uint32_t)(row * 128 + ((c ^ (row & 7)) << 4));
            cp_async16(dst, Bt + (size_t)(bn + row) * ldb + k0 + c * 4);
        }
    };

    float acc[4][4][4];
#pragma unroll
    for (int mt = 0; mt < 4; ++mt)
#pragma unroll
        for (int nt = 0; nt < 4; ++nt)
#pragma unroll
            for (int q = 0; q < 4; ++q) acc[mt][nt][q] = 0.f;

    constexpr int NC = K / 32;             // 32, compile-time
    stage(0, 0); CP_COMMIT();
    stage(1, 1); CP_COMMIT();

#pragma unroll 3
    for (int i = 0; i < NC; ++i) {
        CP_WAIT1();               // this thread's copies of chunk i done
        __syncthreads();          // all threads' copies visible; buf (i+2)%3 free
        if (i + 2 < NC) stage(i + 2, (i + 2) % 3);
        CP_COMMIT();

        const uint32_t sb = smBase + (uint32_t)(i % 3) * STAGE_BYTES;
#pragma unroll
        for (int ks = 0; ks < 4; ++ks) {
            uint32_t a[4][4];
#pragma unroll
            for (int mt = 0; mt < 4; ++mt) {
                const int row = aRow[mt];
                const int c = ks * 2 + aCsel;
                ldsm_x4(a[mt][0], a[mt][1], a[mt][2], a[mt][3],
                        sb + (uint32_t)(row * 128 + ((c ^ (row & 7)) << 4)));
            }
            uint32_t b[4][2];
#pragma unroll
            for (int p = 0; p < 2; ++p) {
                const int row = bRow[p];
                const int c = ks * 2 + bCsel;
                ldsm_x4(b[2 * p][0], b[2 * p][1], b[2 * p + 1][0], b[2 * p + 1][1],
                        sb + 16384u + (uint32_t)(row * 128 + ((c ^ (row & 7)) << 4)));
            }
#pragma unroll
            for (int mt = 0; mt < 4; ++mt)
#pragma unroll
                for (int nt = 0; nt < 4; ++nt)
                    mma_tf32(acc[mt][nt][0], acc[mt][nt][1],
                             acc[mt][nt][2], acc[mt][nt][3],
                             a[mt][0], a[mt][1], a[mt][2], a[mt][3],
                             b[nt][0], b[nt][1]);
        }
    }

    // Epilogue: c0,c1 -> (row, col..col+1); c2,c3 -> (row+8, col..col+1)
#pragma unroll
    for (int mt = 0; mt < 4; ++mt) {
        const int row = bm + warp_m + mt * 16 + g;
#pragma unroll
        for (int nt = 0; nt < 4; ++nt) {
            const int col = bn + warp_n + nt * 8 + 2 * t;
            float v0 = acc[mt][nt][0], v1 = acc[mt][nt][1];
            float v2 = acc[mt][nt][2], v3 = acc[mt][nt][3];
            if (HASBIAS) {
                float b0 = bias[col], b1 = bias[col + 1];
                v0 += b0; v1 += b1; v2 += b0; v3 += b1;
            }
            if (RELU) {
                v0 = fmaxf(v0, 0.f); v1 = fmaxf(v1, 0.f);
                v2 = fmaxf(v2, 0.f); v3 = fmaxf(v3, 0.f);
            }
            *(float2*)(C + (size_t)row * ldc + col) = make_float2(v0, v1);
            *(float2*)(C + (size_t)(row + 8) * ldc + col) = make_float2(v2, v3);
        }
    }
}

// ---------------------------------------------------------------------------
// sim_softmax with tensor-core phase 1 (R12 — unchanged).
// ---------------------------------------------------------------------------
#define SIM_TP    0                        // [128][260] floats (th rows 0..63, ph 64..127)
#define SIM_SS    (128 * 260)              // [64][68]
#define SIM_CX    (SIM_SS + 64 * 68)
#define SIM_CY    (SIM_CX + 64)
#define SIM_SMEM  ((SIM_CY + 64) * 4)      // 151,040 bytes

__global__ void __launch_bounds__(256) sim_softmax_kernel(
    const float* __restrict__ boxes, float* __restrict__ rel)
{
    extern __shared__ float smA[];
    float* sTP = smA + SIM_TP;      // theta rows 0..63, phi rows 64..127, stride 260
    float* sS  = smA + SIM_SS;      // [64][68]
    float* cx  = smA + SIM_CX;
    float* cy  = smA + SIM_CY;

    const int b = blockIdx.x;
    const int tid = threadIdx.x;

    if (tid < 64) {
        const float* bb = boxes + ((size_t)b * 64 + tid) * 4;
        cx[tid] = (bb[0] + bb[2]) * 0.5f;
        cy[tid] = (bb[1] + bb[3]) * 0.5f;
    }

    // Stage theta|phi (RNA-rounded). g_tp row r: 128 float4 (th 0..63, ph 64..127).
    const float4* src4 = (const float4*)(g_tp + (size_t)b * 64 * 512);
    for (int i = tid; i < 64 * 128; i += 256) {
        int r = i >> 7;                // batch row 0..63
        int c4 = i & 127;              // 0..63 theta, 64..127 phi
        float4 v = src4[r * 128 + c4];
        v.x = rna_tf32(v.x); v.y = rna_tf32(v.y);
        v.z = rna_tf32(v.z); v.w = rna_tf32(v.w);
        int row = (c4 < 64) ? r : (64 + r);
        int k4  = (c4 & 63);
        *(float4*)(sTP + row * 260 + k4 * 4) = v;
    }
    __syncthreads();

    // MMA: sim[64,64] = theta @ phi^T. 8 warps: warp_m=(w&1)*32, warp_n=(w>>1)*16.
    const int wid  = tid >> 5;
    const int lane = tid & 31;
    const int g = lane >> 2;
    const int t = lane & 3;
    const int warp_m = (wid & 1) * 32;
    const int warp_n = (wid >> 1) * 16;

    float acc[2][2][4];
#pragma unroll
    for (int mt = 0; mt < 2; ++mt)
#pragma unroll
        for (int nt = 0; nt < 2; ++nt)
#pragma unroll
            for (int q = 0; q < 4; ++q) acc[mt][nt][q] = 0.f;

    const float* sTH = sTP;             // theta rows
    const float* sPH = sTP + 64 * 260;  // phi rows

#pragma unroll 4
    for (int ks = 0; ks < 32; ++ks) {
        const int k0 = ks * 8;
        uint32_t a[2][4];
#pragma unroll
        for (int mt = 0; mt < 2; ++mt) {
            const int r0 = warp_m + mt * 16 + g;
            a[mt][0] = __float_as_uint(sTH[r0 * 260 + k0 + t]);
            a[mt][1] = __float_as_uint(sTH[(r0 + 8) * 260 + k0 + t]);
            a[mt][2] = __float_as_uint(sTH[r0 * 260 + k0 + 4 + t]);
            a[mt][3] = __float_as_uint(sTH[(r0 + 8) * 260 + k0 + 4 + t]);
        }
        uint32_t bf[2][2];
#pragma unroll
        for (int nt = 0; nt < 2; ++nt) {
            const int n = warp_n + nt * 8 + g;
            bf[nt][0] = __float_as_uint(sPH[n * 260 + k0 + t]);
            bf[nt][1] = __float_as_uint(sPH[n * 260 + k0 + 4 + t]);
        }
#pragma unroll
        for (int mt = 0; mt < 2; ++mt)
#pragma unroll
            for (int nt = 0; nt < 2; ++nt)
                mma_tf32(acc[mt][nt][0], acc[mt][nt][1],
                         acc[mt][nt][2], acc[mt][nt][3],
                         a[mt][0], a[mt][1], a[mt][2], a[mt][3],
                         bf[nt][0], bf[nt][1]);
    }

    // write sim/16 into sS
#pragma unroll
    for (int mt = 0; mt < 2; ++mt) {
        const int row = warp_m + mt * 16 + g;
#pragma unroll
        for (int nt = 0; nt < 2; ++nt) {
            const int col = warp_n + nt * 8 + 2 * t;
            sS[row * 68 + col]     = acc[mt][nt][0] * 0.0625f;
            sS[row * 68 + col + 1] = acc[mt][nt][1] * 0.0625f;
            sS[(row + 8) * 68 + col]     = acc[mt][nt][2] * 0.0625f;
            sS[(row + 8) * 68 + col + 1] = acc[mt][nt][3] * 0.0625f;
        }
    }
    __syncthreads();

    // mask + softmax: warp w handles rows 8w..8w+7; lanes cover m (2 each)
    {
        const int w = tid >> 5;
        const int ln = tid & 31;
        const float thr2 = (0.2f * 157.0f) * (0.2f * 157.0f);
#pragma unroll
        for (int r = 0; r < 8; ++r) {
            const int n = w * 8 + r;
            const float cxn = cx[n], cyn = cy[n];
            float dx0 = cxn - cx[ln], dy0 = cyn - cy[ln];
            float dx1 = cxn - cx[ln + 32], dy1 = cyn - cy[ln + 32];
            float v0 = (dx0 * dx0 + dy0 * dy0 > thr2) ? -INFINITY : sS[n * 68 + ln];
            float v1 = (dx1 * dx1 + dy1 * dy1 > thr2) ? -INFINITY : sS[n * 68 + ln + 32];
            float mx = fmaxf(v0, v1);
#pragma unroll
            for (int o = 16; o; o >>= 1)
                mx = fmaxf(mx, __shfl_xor_sync(0xFFFFFFFFu, mx, o));
            float e0 = expf(v0 - mx);
            float e1 = expf(v1 - mx);
            float s = e0 + e1;
#pragma unroll
            for (int o = 16; o; o >>= 1)
                s += __shfl_xor_sync(0xFFFFFFFFu, s, o);
            const float inv = 1.f / s;
            sS[n * 68 + ln] = e0 * inv;
            sS[n * 68 + ln + 32] = e1 * inv;
        }
    }
    __syncthreads();

    float* ro = rel + (size_t)b * 4096;
    for (int i = tid; i < 4096; i += 256)
        ro[i] = sS[(i >> 6) * 68 + (i & 63)];
}

// ---------------------------------------------------------------------------
// agg = relation[64,64] @ feats[64,1024] via tf32 mma.sync (R9/R12 — best).
// CTA = (batch, 256-col chunk), 256 threads = 8 warps, warp tile 64x32, K=64.
// ---------------------------------------------------------------------------
#define AGG_SMEM ((64 * 264 + 64 * 68) * 4)   // 84992

__global__ void __launch_bounds__(256) agg_kernel(
    const float* __restrict__ feats, const float* __restrict__ rel,
    float* __restrict__ agg)
{
    extern __shared__ float smA[];
    float* sfeats = smA;                 // [64][264]  ([m][f])
    float* srel   = smA + 64 * 264;      // [64][68]   ([n][m])

    const int b = blockIdx.x;
    const int fchunk = blockIdx.y * 256;
    const int tid = threadIdx.x;

    // stage feats (RNA-rounded to tf32)
    const float4* fsrc = (const float4*)(feats + (size_t)b * 64 * 1024 + fchunk);
#pragma unroll
    for (int r = 0; r < 16; ++r) {
        int idx = tid + 256 * r;        // 0..4095 float4s
        int m = idx >> 6, c4 = idx & 63;
        float4 v = fsrc[(size_t)m * 256 + c4];
        v.x = rna_tf32(v.x); v.y = rna_tf32(v.y);
        v.z = rna_tf32(v.z); v.w = rna_tf32(v.w);
        *(float4*)(sfeats + m * 264 + c4 * 4) = v;
    }
    // stage rel (RNA-rounded to tf32)
    const float4* rsrc = (const float4*)(rel + (size_t)b * 4096);
#pragma unroll
    for (int r = 0; r < 4; ++r) {
        int idx = tid + 256 * r;        // 0..1023 float4s
        int n = idx >> 4, c4 = idx & 15;
        float4 v = rsrc[idx];
        v.x = rna_tf32(v.x); v.y = rna_tf32(v.y);
        v.z = rna_tf32(v.z); v.w = rna_tf32(v.w);
        *(float4*)(srel + n * 68 + c4 * 4) = v;
    }
    __syncthreads();

    const int wid  = tid >> 5;
    const int lane = tid & 31;
    const int g = lane >> 2;
    const int t = lane & 3;
    const int warp_n = wid * 32;         // f-offset within 256 chunk

    float acc[4][4][4];
#pragma unroll
    for (int mt = 0; mt < 4; ++mt)
#pragma unroll
        for (int nt = 0; nt < 4; ++nt)
#pragma unroll
            for (int q = 0; q < 4; ++q) acc[mt][nt][q] = 0.f;

#pragma unroll
    for (int ks = 0; ks < 8; ++ks) {
        const int k0 = ks * 8;
        uint32_t a[4][4];
#pragma unroll
        for (int mt = 0; mt < 4; ++mt) {
            a[mt][0] = __float_as_uint(srel[(mt * 16 + g) * 68 + k0 + t]);
            a[mt][1] = __float_as_uint(srel[(mt * 16 + 8 + g) * 68 + k0 + t]);
            a[mt][2] = __float_as_uint(srel[(mt * 16 + g) * 68 + k0 + 4 + t]);
            a[mt][3] = __float_as_uint(srel[(mt * 16 + 8 + g) * 68 + k0 + 4 + t]);
        }
        uint32_t bf[4][2];
#pragma unroll
        for (int nt = 0; nt < 4; ++nt) {
            bf[nt][0] = __float_as_uint(sfeats[(k0 + t) * 264 + warp_n + nt * 8 + g]);
            bf[nt][1] = __float_as_uint(sfeats[(k0 + 4 + t) * 264 + warp_n + nt * 8 + g]);
        }
#pragma unroll
        for (int mt = 0; mt < 4; ++mt)
#pragma unroll
            for (int nt = 0; nt < 4; ++nt)
                mma_tf32(acc[mt][nt][0], acc[mt][nt][1],
                         acc[mt][nt][2], acc[mt][nt][3],
                         a[mt][0], a[mt][1], a[mt][2], a[mt][3],
                         bf[nt][0], bf[nt][1]);
    }

    // Epilogue: RNA-round for gemm2 consumption
#pragma unroll
    for (int mt = 0; mt < 4; ++mt) {
        const size_t row0 = (size_t)b * 64 + mt * 16 + g;
#pragma unroll
        for (int nt = 0; nt < 4; ++nt) {
            const int col = fchunk + warp_n + nt * 8 + 2 * t;
            float2 p0 = make_float2(rna_tf32(acc[mt][nt][0]), rna_tf32(acc[mt][nt][1]));
            float2 p1 = make_float2(rna_tf32(acc[mt][nt][2]), rna_tf32(acc[mt][nt][3]));
            *(float2*)(agg + row0 * 1024 + col) = p0;
            *(float2*)(agg + (row0 + 8) * 1024 + col) = p1;
        }
    }
}

// ---------------------------------------------------------------------------
extern "C" void kernel_launch(void* const* d_in, const int* in_sizes, int n_in,
                              void* d_out, int out_size)
{
    const float* feats = (const float*)d_in[0];
    const float* boxes = (const float*)d_in[1];
    const float* Wth   = (const float*)d_in[2];
    const float* bth   = (const float*)d_in[3];
    const float* Wph   = (const float*)d_in[4];
    const float* bph   = (const float*)d_in[5];
    const float* Wg    = (const float*)d_in[6];
    float* out = (float*)d_out;

    float *tp, *agg, *relScratch, *wtp, *wg, *bias;
    cudaGetSymbolAddress((void**)&tp, g_tp);
    cudaGetSymbolAddress((void**)&agg, g_agg);
    cudaGetSymbolAddress((void**)&relScratch, g_rel);
    cudaGetSymbolAddress((void**)&wtp, g_wtp);
    cudaGetSymbolAddress((void**)&wg, g_wg);
    cudaGetSymbolAddress((void**)&bias, g_bias);

    cudaFuncSetAttribute(gemm_tf32<0, 1, 1024>,
                         cudaFuncAttributeMaxDynamicSharedMemorySize, GEMM_SMEM);
    cudaFuncSetAttribute(gemm_tf32<1, 0, 1024>,
                         cudaFuncAttributeMaxDynamicSharedMemorySize, GEMM_SMEM);
    cudaFuncSetAttribute(sim_softmax_kernel,
                         cudaFuncAttributeMaxDynamicSharedMemorySize, SIM_SMEM);
    cudaFuncSetAttribute(agg_kernel,
                         cudaFuncAttributeMaxDynamicSharedMemorySize, AGG_SMEM);

    float* rel = ((size_t)out_size >= OUT_ELEMS + REL_ELEMS)
                     ? out + OUT_ELEMS
                     : relScratch;

    // 5 launches; agg sits in the ncu capture slot (#4).
    prep_all_kernel<<<1537, dim3(32, 8)>>>(Wth, Wph, Wg, bth, bph, wtp, wg, bias); // 1
    gemm_tf32<0, 1, 1024><<<dim3(4, 256), 256, GEMM_SMEM>>>(                       // 2
        feats, NFG, wtp, NFG, bias, tp, 512);
    sim_softmax_kernel<<<BB, 256, SIM_SMEM>>>(boxes, rel);                         // 3
    agg_kernel<<<dim3(BB, 4), 256, AGG_SMEM>>>(feats, rel, agg);                   // 4
    gemm_tf32<1, 0, 1024><<<dim3(8, 256), 256, GEMM_SMEM>>>(                       // 5
        agg, NFG, wg, NFG, nullptr, out, NFG);
}

// round 15
// speedup vs baseline: 1.1132x; 1.0292x over previous
#include <cuda_runtime.h>
#include <math.h>
#include <stdint.h>

// Problem constants (fixed shapes)
#define BB    512
#define NN    64
#define NFG   1024
#define NFR   256
#define MTOT  (BB * NN)                          // 32768
#define OUT_ELEMS  ((size_t)MTOT * NFG)          // 33554432
#define REL_ELEMS  ((size_t)BB * NN * NN)        // 2097152

// Scratch (device globals — allocation-free)
__device__ float g_tp[(size_t)MTOT * 512];       // theta (cols 0..255) | phi (256..511)
__device__ float g_agg[(size_t)MTOT * NFG];      // relation @ feats (tf32-rounded)
__device__ float g_rel[REL_ELEMS];               // fallback relation scratch
__device__ float g_wtp[(size_t)512 * 1024];      // [N=512][K=1024] = [WthT;WphT], tf32-rounded
__device__ float g_wg[(size_t)1024 * 1024];      // WgT [N][K], tf32-rounded
__device__ float g_bias[512];                    // concat(b_theta, b_phi)

// ---------------------------------------------------------------------------
// Helpers (all compute_80-era PTX or older — legal at compute_103)
// ---------------------------------------------------------------------------
__device__ __forceinline__ uint32_t smem_u32(const void* p) {
    uint32_t a;
    asm("{ .reg .u64 t; cvta.to.shared.u64 t, %1; cvt.u32.u64 %0, t; }" : "=r"(a) : "l"(p));
    return a;
}
__device__ __forceinline__ float rna_tf32(float x) {
    uint32_t r;
    asm("cvt.rna.tf32.f32 %0, %1;" : "=r"(r) : "f"(x));
    return __uint_as_float(r);
}
__device__ __forceinline__ uint32_t rna_tf32_u(float x) {
    uint32_t r;
    asm("cvt.rna.tf32.f32 %0, %1;" : "=r"(r) : "f"(x));
    return r;
}
__device__ __forceinline__ void cp_async16(uint32_t dst, const void* src) {
    asm volatile("cp.async.cg.shared.global [%0], [%1], 16;" :: "r"(dst), "l"(src));
}
#define CP_COMMIT() asm volatile("cp.async.commit_group;" ::: "memory")
#define CP_WAIT1()  asm volatile("cp.async.wait_group 1;" ::: "memory")
#define CP_WAIT0()  asm volatile("cp.async.wait_group 0;" ::: "memory")

__device__ __forceinline__ void ldsm_x4(uint32_t& r0, uint32_t& r1,
                                        uint32_t& r2, uint32_t& r3, uint32_t addr) {
    asm volatile("ldmatrix.sync.aligned.m8n8.x4.shared.b16 {%0,%1,%2,%3}, [%4];"
                 : "=r"(r0), "=r"(r1), "=r"(r2), "=r"(r3) : "r"(addr));
}

__device__ __forceinline__ void mma_tf32(float& d0, float& d1, float& d2, float& d3,
                                         uint32_t a0, uint32_t a1, uint32_t a2, uint32_t a3,
                                         uint32_t b0, uint32_t b1) {
    asm volatile(
        "mma.sync.aligned.m16n8k8.row.col.f32.tf32.tf32.f32 "
        "{%0,%1,%2,%3}, {%4,%5,%6,%7}, {%8,%9}, {%0,%1,%2,%3};"
        : "+f"(d0), "+f"(d1), "+f"(d2), "+f"(d3)
        : "r"(a0), "r"(a1), "r"(a2), "r"(a3), "r"(b0), "r"(b1));
}

// ---------------------------------------------------------------------------
// Fused prologue: all weight transposes (+ tf32 rounding) + bias concat
// in ONE launch. Blocks 0..255: Wth; 256..511: Wph; 512..1535: Wg; 1536: bias.
// ---------------------------------------------------------------------------
__global__ void prep_all_kernel(const float* __restrict__ Wth,
                                const float* __restrict__ Wph,
                                const float* __restrict__ Wg,
                                const float* __restrict__ bth,
                                const float* __restrict__ bph,
                                float* __restrict__ wtp,
                                float* __restrict__ wg,
                                float* __restrict__ bias)
{
    __shared__ float tile[32][33];
    const int b = blockIdx.x;
    const int tx = threadIdx.x, ty = threadIdx.y;   // 32 x 8

    if (b >= 1536) {
        int i = ty * 32 + tx;          // 0..255
        bias[i] = bth[i];
        bias[i + 256] = bph[i];
        return;
    }

    const float* src;
    float* dst;
    int K, N, n0, k0;
    if (b < 256) {
        src = Wth; dst = wtp; K = 1024; N = 256;
        n0 = (b & 7) * 32; k0 = (b >> 3) * 32;
    } else if (b < 512) {
        int t = b - 256;
        src = Wph; dst = wtp + (size_t)256 * 1024; K = 1024; N = 256;
        n0 = (t & 7) * 32; k0 = (t >> 3) * 32;
    } else {
        int t = b - 512;
        src = Wg; dst = wg; K = 1024; N = 1024;
        n0 = (t & 31) * 32; k0 = (t >> 5) * 32;
    }
#pragma unroll
    for (int r = 0; r < 32; r += 8)
        tile[ty + r][tx] = src[(size_t)(k0 + ty + r) * N + n0 + tx];
    __syncthreads();
#pragma unroll
    for (int r = 0; r < 32; r += 8)
        dst[(size_t)(n0 + ty + r) * K + k0 + tx] = rna_tf32(tile[tx][ty + r]);
}

// ---------------------------------------------------------------------------
// tf32 mma.sync GEMM with ldmatrix fragments (R14 configuration — best).
// C[M,N] = op(A[M,K] @ Bt[N,K]^T) (+bias) (relu). K compile-time (1024).
// CTA 128x128, BK=32, 3-stage cp.async, 256 threads (8 warps 2x4,
// warp tile 64x32, 4x4 m16n8k8 per k-step), 2 CTAs/SM, unroll-3 chunk loop.
// Bt pre-rounded to tf32; A consumed raw (HMMA truncation, ~6e-5 rel bias).
// ---------------------------------------------------------------------------
#define STAGE_BYTES 32768u                 // A 16KB + B 16KB
#define GEMM_SMEM   (3 * 32768)            // 98304 bytes -> 2 CTAs/SM

template <int RELU, int HASBIAS, int K>
__global__ void __launch_bounds__(256) gemm_tf32(
    const float* __restrict__ A, int lda,
    const float* __restrict__ Bt, int ldb,
    const float* __restrict__ bias,
    float* __restrict__ C, int ldc)
{
    extern __shared__ float sm[];
    const uint32_t smBase = smem_u32(sm);

    const int tid = threadIdx.x;
    const int bm = blockIdx.y * 128;
    const int bn = blockIdx.x * 128;

    const int wid  = tid >> 5;
    const int lane = tid & 31;
    const int g = lane >> 2;                // MMA groupID
    const int t = lane & 3;                 // MMA threadID_in_group
    const int warp_m = (wid & 1) * 64;
    const int warp_n = (wid >> 1) * 32;

    // ldmatrix per-lane row indices (within 128-row tile)
    const int aRow[4] = {
        warp_m + 0 * 16 + (lane & 7) + ((lane >> 3) & 1) * 8,
        warp_m + 1 * 16 + (lane & 7) + ((lane >> 3) & 1) * 8,
        warp_m + 2 * 16 + (lane & 7) + ((lane >> 3) & 1) * 8,
        warp_m + 3 * 16 + (lane & 7) + ((lane >> 3) & 1) * 8 };
    const int aCsel = lane >> 4;            // 0/1 -> k chunk lo/hi
    const int bRow[2] = {
        warp_n + (0 + ((lane >> 4) & 1)) * 8 + (lane & 7),
        warp_n + (2 + ((lane >> 4) & 1)) * 8 + (lane & 7) };
    const int bCsel = (lane >> 3) & 1;

    // stage one BK=32 chunk into buffer s (8 x cp.async 16B per thread)
    auto stage = [&](int kc, int s) {
        const int k0 = kc * 32;
        const uint32_t base = smBase + (uint32_t)s * STAGE_BYTES;
#pragma unroll
        for (int r = 0; r < 4; ++r) {
            int idx = tid + 256 * r;               // 0..1023
            int row = idx >> 3, c = idx & 7;
            uint32_t dst = base + (uint32_t)(row * 128 + ((c ^ (row & 7)) << 4));
            cp_async16(dst, A + (size_t)(bm + row) * lda + k0 + c * 4);
        }
#pragma unroll
        for (int r = 0; r < 4; ++r) {
            int idx = tid + 256 * r;
            int row = idx >> 3, c = idx & 7;
            uint32_t dst = base + 16384u + (uint32_t)(row * 128 + ((c ^ (row & 7)) << 4));
            cp_async16(dst, Bt + (size_t)(bn + row) * ldb + k0 + c * 4);
        }
    };

    float acc[4][4][4];
#pragma unroll
    for (int mt = 0; mt < 4; ++mt)
#pragma unroll
        for (int nt = 0; nt < 4; ++nt)
#pragma unroll
            for (int q = 0; q < 4; ++q) acc[mt][nt][q] = 0.f;

    constexpr int NC = K / 32;             // 32, compile-time
    stage(0, 0); CP_COMMIT();
    stage(1, 1); CP_COMMIT();

#pragma unroll 3
    for (int i = 0; i < NC; ++i) {
        CP_WAIT1();               // this thread's copies of chunk i done
        __syncthreads();          // all threads' copies visible; buf (i+2)%3 free
        if (i + 2 < NC) stage(i + 2, (i + 2) % 3);
        CP_COMMIT();

        const uint32_t sb = smBase + (uint32_t)(i % 3) * STAGE_BYTES;
#pragma unroll
        for (int ks = 0; ks < 4; ++ks) {
            uint32_t a[4][4];
#pragma unroll
            for (int mt = 0; mt < 4; ++mt) {
                const int row = aRow[mt];
                const int c = ks * 2 + aCsel;
                ldsm_x4(a[mt][0], a[mt][1], a[mt][2], a[mt][3],
                        sb + (uint32_t)(row * 128 + ((c ^ (row & 7)) << 4)));
            }
            uint32_t b[4][2];
#pragma unroll
            for (int p = 0; p < 2; ++p) {
                const int row = bRow[p];
                const int c = ks * 2 + bCsel;
                ldsm_x4(b[2 * p][0], b[2 * p][1], b[2 * p + 1][0], b[2 * p + 1][1],
                        sb + 16384u + (uint32_t)(row * 128 + ((c ^ (row & 7)) << 4)));
            }
#pragma unroll
            for (int mt = 0; mt < 4; ++mt)
#pragma unroll
                for (int nt = 0; nt < 4; ++nt)
                    mma_tf32(acc[mt][nt][0], acc[mt][nt][1],
                             acc[mt][nt][2], acc[mt][nt][3],
                             a[mt][0], a[mt][1], a[mt][2], a[mt][3],
                             b[nt][0], b[nt][1]);
        }
    }

    // Epilogue: c0,c1 -> (row, col..col+1); c2,c3 -> (row+8, col..col+1)
#pragma unroll
    for (int mt = 0; mt < 4; ++mt) {
        const int row = bm + warp_m + mt * 16 + g;
#pragma unroll
        for (int nt = 0; nt < 4; ++nt) {
            const int col = bn + warp_n + nt * 8 + 2 * t;
            float v0 = acc[mt][nt][0], v1 = acc[mt][nt][1];
            float v2 = acc[mt][nt][2], v3 = acc[mt][nt][3];
            if (HASBIAS) {
                float b0 = bias[col], b1 = bias[col + 1];
                v0 += b0; v1 += b1; v2 += b0; v3 += b1;
            }
            if (RELU) {
                v0 = fmaxf(v0, 0.f); v1 = fmaxf(v1, 0.f);
                v2 = fmaxf(v2, 0.f); v3 = fmaxf(v3, 0.f);
            }
            *(float2*)(C + (size_t)row * ldc + col) = make_float2(v0, v1);
            *(float2*)(C + (size_t)(row + 8) * ldc + col) = make_float2(v2, v3);
        }
    }
}

// ---------------------------------------------------------------------------
// sim_softmax with tensor-core phase 1 (R12 — unchanged).
// ---------------------------------------------------------------------------
#define SIM_TP    0                        // [128][260] floats (th rows 0..63, ph 64..127)
#define SIM_SS    (128 * 260)              // [64][68]
#define SIM_CX    (SIM_SS + 64 * 68)
#define SIM_CY    (SIM_CX + 64)
#define SIM_SMEM  ((SIM_CY + 64) * 4)      // 151,040 bytes

__global__ void __launch_bounds__(256) sim_softmax_kernel(
    const float* __restrict__ boxes, float* __restrict__ rel)
{
    extern __shared__ float smA[];
    float* sTP = smA + SIM_TP;      // theta rows 0..63, phi rows 64..127, stride 260
    float* sS  = smA + SIM_SS;      // [64][68]
    float* cx  = smA + SIM_CX;
    float* cy  = smA + SIM_CY;

    const int b = blockIdx.x;
    const int tid = threadIdx.x;

    if (tid < 64) {
        const float* bb = boxes + ((size_t)b * 64 + tid) * 4;
        cx[tid] = (bb[0] + bb[2]) * 0.5f;
        cy[tid] = (bb[1] + bb[3]) * 0.5f;
    }

    // Stage theta|phi (RNA-rounded). g_tp row r: 128 float4 (th 0..63, ph 64..127).
    const float4* src4 = (const float4*)(g_tp + (size_t)b * 64 * 512);
    for (int i = tid; i < 64 * 128; i += 256) {
        int r = i >> 7;                // batch row 0..63
        int c4 = i & 127;              // 0..63 theta, 64..127 phi
        float4 v = src4[r * 128 + c4];
        v.x = rna_tf32(v.x); v.y = rna_tf32(v.y);
        v.z = rna_tf32(v.z); v.w = rna_tf32(v.w);
        int row = (c4 < 64) ? r : (64 + r);
        int k4  = (c4 & 63);
        *(float4*)(sTP + row * 260 + k4 * 4) = v;
    }
    __syncthreads();

    // MMA: sim[64,64] = theta @ phi^T. 8 warps: warp_m=(w&1)*32, warp_n=(w>>1)*16.
    const int wid  = tid >> 5;
    const int lane = tid & 31;
    const int g = lane >> 2;
    const int t = lane & 3;
    const int warp_m = (wid & 1) * 32;
    const int warp_n = (wid >> 1) * 16;

    float acc[2][2][4];
#pragma unroll
    for (int mt = 0; mt < 2; ++mt)
#pragma unroll
        for (int nt = 0; nt < 2; ++nt)
#pragma unroll
            for (int q = 0; q < 4; ++q) acc[mt][nt][q] = 0.f;

    const float* sTH = sTP;             // theta rows
    const float* sPH = sTP + 64 * 260;  // phi rows

#pragma unroll 4
    for (int ks = 0; ks < 32; ++ks) {
        const int k0 = ks * 8;
        uint32_t a[2][4];
#pragma unroll
        for (int mt = 0; mt < 2; ++mt) {
            const int r0 = warp_m + mt * 16 + g;
            a[mt][0] = __float_as_uint(sTH[r0 * 260 + k0 + t]);
            a[mt][1] = __float_as_uint(sTH[(r0 + 8) * 260 + k0 + t]);
            a[mt][2] = __float_as_uint(sTH[r0 * 260 + k0 + 4 + t]);
            a[mt][3] = __float_as_uint(sTH[(r0 + 8) * 260 + k0 + 4 + t]);
        }
        uint32_t bf[2][2];
#pragma unroll
        for (int nt = 0; nt < 2; ++nt) {
            const int n = warp_n + nt * 8 + g;
            bf[nt][0] = __float_as_uint(sPH[n * 260 + k0 + t]);
            bf[nt][1] = __float_as_uint(sPH[n * 260 + k0 + 4 + t]);
        }
#pragma unroll
        for (int mt = 0; mt < 2; ++mt)
#pragma unroll
            for (int nt = 0; nt < 2; ++nt)
                mma_tf32(acc[mt][nt][0], acc[mt][nt][1],
                         acc[mt][nt][2], acc[mt][nt][3],
                         a[mt][0], a[mt][1], a[mt][2], a[mt][3],
                         bf[nt][0], bf[nt][1]);
    }

    // write sim/16 into sS
#pragma unroll
    for (int mt = 0; mt < 2; ++mt) {
        const int row = warp_m + mt * 16 + g;
#pragma unroll
        for (int nt = 0; nt < 2; ++nt) {
            const int col = warp_n + nt * 8 + 2 * t;
            sS[row * 68 + col]     = acc[mt][nt][0] * 0.0625f;
            sS[row * 68 + col + 1] = acc[mt][nt][1] * 0.0625f;
            sS[(row + 8) * 68 + col]     = acc[mt][nt][2] * 0.0625f;
            sS[(row + 8) * 68 + col + 1] = acc[mt][nt][3] * 0.0625f;
        }
    }
    __syncthreads();

    // mask + softmax: warp w handles rows 8w..8w+7; lanes cover m (2 each)
    {
        const int w = tid >> 5;
        const int ln = tid & 31;
        const float thr2 = (0.2f * 157.0f) * (0.2f * 157.0f);
#pragma unroll
        for (int r = 0; r < 8; ++r) {
            const int n = w * 8 + r;
            const float cxn = cx[n], cyn = cy[n];
            float dx0 = cxn - cx[ln], dy0 = cyn - cy[ln];
            float dx1 = cxn - cx[ln + 32], dy1 = cyn - cy[ln + 32];
            float v0 = (dx0 * dx0 + dy0 * dy0 > thr2) ? -INFINITY : sS[n * 68 + ln];
            float v1 = (dx1 * dx1 + dy1 * dy1 > thr2) ? -INFINITY : sS[n * 68 + ln + 32];
            float mx = fmaxf(v0, v1);
#pragma unroll
            for (int o = 16; o; o >>= 1)
                mx = fmaxf(mx, __shfl_xor_sync(0xFFFFFFFFu, mx, o));
            float e0 = expf(v0 - mx);
            float e1 = expf(v1 - mx);
            float s = e0 + e1;
#pragma unroll
            for (int o = 16; o; o >>= 1)
                s += __shfl_xor_sync(0xFFFFFFFFu, s, o);
            const float inv = 1.f / s;
            sS[n * 68 + ln] = e0 * inv;
            sS[n * 68 + ln + 32] = e1 * inv;
        }
    }
    __syncthreads();

    float* ro = rel + (size_t)b * 4096;
    for (int i = tid; i < 4096; i += 256)
        ro[i] = sS[(i >> 6) * 68 + (i & 63)];
}

// ---------------------------------------------------------------------------
// agg = relation[64,64] @ feats[64,1024] via tf32 mma.sync.
// R15: staging via cp.async (raw values); RNA rounding moved to the fragment
// LDS reads -> bit-identical MMA inputs, but staging is fire-and-forget
// (full MLP, no LDG scoreboard stall in front of the barrier).
// CTA = (batch, 256-col chunk), 256 threads = 8 warps, warp tile 64x32, K=64.
// ---------------------------------------------------------------------------
#define AGG_SMEM ((64 * 264 + 64 * 68) * 4)   // 84992

__global__ void __launch_bounds__(256) agg_kernel(
    const float* __restrict__ feats, const float* __restrict__ rel,
    float* __restrict__ agg)
{
    extern __shared__ float smA[];
    float* sfeats = smA;                 // [64][264]  ([m][f]) raw fp32
    float* srel   = smA + 64 * 264;      // [64][68]   ([n][m]) raw fp32
    const uint32_t sfA = smem_u32(sfeats);
    const uint32_t srA = smem_u32(srel);

    const int b = blockIdx.x;
    const int fchunk = blockIdx.y * 256;
    const int tid = threadIdx.x;

    // stage feats chunk via cp.async (raw)
    const float* fsrc = feats + (size_t)b * 64 * 1024 + fchunk;
#pragma unroll
    for (int r = 0; r < 16; ++r) {
        int idx = tid + 256 * r;        // 0..4095 float4s
        int m = idx >> 6, c4 = idx & 63;
        cp_async16(sfA + (uint32_t)(m * 264 + c4 * 4) * 4,
                   fsrc + (size_t)m * 1024 + c4 * 4);
    }
    // stage rel via cp.async (raw)
    const float* rsrc = rel + (size_t)b * 4096;
#pragma unroll
    for (int r = 0; r < 4; ++r) {
        int idx = tid + 256 * r;        // 0..1023 float4s
        int n = idx >> 4, c4 = idx & 15;
        cp_async16(srA + (uint32_t)(n * 68 + c4 * 4) * 4,
                   rsrc + idx * 4);
    }
    CP_COMMIT();
    CP_WAIT0();
    __syncthreads();

    const int wid  = tid >> 5;
    const int lane = tid & 31;
    const int g = lane >> 2;
    const int t = lane & 3;
    const int warp_n = wid * 32;         // f-offset within 256 chunk

    float acc[4][4][4];
#pragma unroll
    for (int mt = 0; mt < 4; ++mt)
#pragma unroll
        for (int nt = 0; nt < 4; ++nt)
#pragma unroll
            for (int q = 0; q < 4; ++q) acc[mt][nt][q] = 0.f;

#pragma unroll
    for (int ks = 0; ks < 8; ++ks) {
        const int k0 = ks * 8;
        uint32_t a[4][4];
#pragma unroll
        for (int mt = 0; mt < 4; ++mt) {
            a[mt][0] = rna_tf32_u(srel[(mt * 16 + g) * 68 + k0 + t]);
            a[mt][1] = rna_tf32_u(srel[(mt * 16 + 8 + g) * 68 + k0 + t]);
            a[mt][2] = rna_tf32_u(srel[(mt * 16 + g) * 68 + k0 + 4 + t]);
            a[mt][3] = rna_tf32_u(srel[(mt * 16 + 8 + g) * 68 + k0 + 4 + t]);
        }
        uint32_t bf[4][2];
#pragma unroll
        for (int nt = 0; nt < 4; ++nt) {
            bf[nt][0] = rna_tf32_u(sfeats[(k0 + t) * 264 + warp_n + nt * 8 + g]);
            bf[nt][1] = rna_tf32_u(sfeats[(k0 + 4 + t) * 264 + warp_n + nt * 8 + g]);
        }
#pragma unroll
        for (int mt = 0; mt < 4; ++mt)
#pragma unroll
            for (int nt = 0; nt < 4; ++nt)
                mma_tf32(acc[mt][nt][0], acc[mt][nt][1],
                         acc[mt][nt][2], acc[mt][nt][3],
                         a[mt][0], a[mt][1], a[mt][2], a[mt][3],
                         bf[nt][0], bf[nt][1]);
    }

    // Epilogue: RNA-round for gemm2 consumption
#pragma unroll
    for (int mt = 0; mt < 4; ++mt) {
        const size_t row0 = (size_t)b * 64 + mt * 16 + g;
#pragma unroll
        for (int nt = 0; nt < 4; ++nt) {
            const int col = fchunk + warp_n + nt * 8 + 2 * t;
            float2 p0 = make_float2(rna_tf32(acc[mt][nt][0]), rna_tf32(acc[mt][nt][1]));
            float2 p1 = make_float2(rna_tf32(acc[mt][nt][2]), rna_tf32(acc[mt][nt][3]));
            *(float2*)(agg + row0 * 1024 + col) = p0;
            *(float2*)(agg + (row0 + 8) * 1024 + col) = p1;
        }
    }
}

// ---------------------------------------------------------------------------
extern "C" void kernel_launch(void* const* d_in, const int* in_sizes, int n_in,
                              void* d_out, int out_size)
{
    const float* feats = (const float*)d_in[0];
    const float* boxes = (const float*)d_in[1];
    const float* Wth   = (const float*)d_in[2];
    const float* bth   = (const float*)d_in[3];
    const float* Wph   = (const float*)d_in[4];
    const float* bph   = (const float*)d_in[5];
    const float* Wg    = (const float*)d_in[6];
    float* out = (float*)d_out;

    float *tp, *agg, *relScratch, *wtp, *wg, *bias;
    cudaGetSymbolAddress((void**)&tp, g_tp);
    cudaGetSymbolAddress((void**)&agg, g_agg);
    cudaGetSymbolAddress((void**)&relScratch, g_rel);
    cudaGetSymbolAddress((void**)&wtp, g_wtp);
    cudaGetSymbolAddress((void**)&wg, g_wg);
    cudaGetSymbolAddress((void**)&bias, g_bias);

    cudaFuncSetAttribute(gemm_tf32<0, 1, 1024>,
                         cudaFuncAttributeMaxDynamicSharedMemorySize, GEMM_SMEM);
    cudaFuncSetAttribute(gemm_tf32<1, 0, 1024>,
                         cudaFuncAttributeMaxDynamicSharedMemorySize, GEMM_SMEM);
    cudaFuncSetAttribute(sim_softmax_kernel,
                         cudaFuncAttributeMaxDynamicSharedMemorySize, SIM_SMEM);
    cudaFuncSetAttribute(agg_kernel,
                         cudaFuncAttributeMaxDynamicSharedMemorySize, AGG_SMEM);

    float* rel = ((size_t)out_size >= OUT_ELEMS + REL_ELEMS)
                     ? out + OUT_ELEMS
                     : relScratch;

    // 5 launches; agg sits in the ncu capture slot (#4).
    prep_all_kernel<<<1537, dim3(32, 8)>>>(Wth, Wph, Wg, bth, bph, wtp, wg, bias); // 1
    gemm_tf32<0, 1, 1024><<<dim3(4, 256), 256, GEMM_SMEM>>>(                       // 2
        feats, NFG, wtp, NFG, bias, tp, 512);
    sim_softmax_kernel<<<BB, 256, SIM_SMEM>>>(boxes, rel);                         // 3
    agg_kernel<<<dim3(BB, 4), 256, AGG_SMEM>>>(feats, rel, agg);                   // 4
    gemm_tf32<1, 0, 1024><<<dim3(8, 256), 256, GEMM_SMEM>>>(                       // 5
        agg, NFG, wg, NFG, nullptr, out, NFG);
}

// round 16
// speedup vs baseline: 1.1339x; 1.0186x over previous
#include <cuda_runtime.h>
#include <math.h>
#include <stdint.h>

// Problem constants (fixed shapes)
#define BB    512
#define NN    64
#define NFG   1024
#define NFR   256
#define MTOT  (BB * NN)                          // 32768
#define OUT_ELEMS  ((size_t)MTOT * NFG)          // 33554432
#define REL_ELEMS  ((size_t)BB * NN * NN)        // 2097152

// Scratch (device globals — allocation-free)
__device__ float g_tp[(size_t)MTOT * 512];       // theta|phi, RNA-tf32-rounded by gemm1
__device__ float g_agg[(size_t)MTOT * NFG];      // relation @ feats (tf32-rounded)
__device__ float g_rel[REL_ELEMS];               // fallback relation scratch
__device__ float g_wtp[(size_t)512 * 1024];      // [N=512][K=1024] = [WthT;WphT], tf32-rounded
__device__ float g_wg[(size_t)1024 * 1024];      // WgT [N][K], tf32-rounded
__device__ float g_bias[512];                    // concat(b_theta, b_phi)

// ---------------------------------------------------------------------------
// Helpers (all compute_80-era PTX or older — legal at compute_103)
// ---------------------------------------------------------------------------
__device__ __forceinline__ uint32_t smem_u32(const void* p) {
    uint32_t a;
    asm("{ .reg .u64 t; cvta.to.shared.u64 t, %1; cvt.u32.u64 %0, t; }" : "=r"(a) : "l"(p));
    return a;
}
__device__ __forceinline__ float rna_tf32(float x) {
    uint32_t r;
    asm("cvt.rna.tf32.f32 %0, %1;" : "=r"(r) : "f"(x));
    return __uint_as_float(r);
}
__device__ __forceinline__ uint32_t rna_tf32_u(float x) {
    uint32_t r;
    asm("cvt.rna.tf32.f32 %0, %1;" : "=r"(r) : "f"(x));
    return r;
}
__device__ __forceinline__ void cp_async16(uint32_t dst, const void* src) {
    asm volatile("cp.async.cg.shared.global [%0], [%1], 16;" :: "r"(dst), "l"(src));
}
#define CP_COMMIT() asm volatile("cp.async.commit_group;" ::: "memory")
#define CP_WAIT1()  asm volatile("cp.async.wait_group 1;" ::: "memory")
#define CP_WAIT0()  asm volatile("cp.async.wait_group 0;" ::: "memory")

__device__ __forceinline__ void ldsm_x4(uint32_t& r0, uint32_t& r1,
                                        uint32_t& r2, uint32_t& r3, uint32_t addr) {
    asm volatile("ldmatrix.sync.aligned.m8n8.x4.shared.b16 {%0,%1,%2,%3}, [%4];"
                 : "=r"(r0), "=r"(r1), "=r"(r2), "=r"(r3) : "r"(addr));
}

__device__ __forceinline__ void mma_tf32(float& d0, float& d1, float& d2, float& d3,
                                         uint32_t a0, uint32_t a1, uint32_t a2, uint32_t a3,
                                         uint32_t b0, uint32_t b1) {
    asm volatile(
        "mma.sync.aligned.m16n8k8.row.col.f32.tf32.tf32.f32 "
        "{%0,%1,%2,%3}, {%4,%5,%6,%7}, {%8,%9}, {%0,%1,%2,%3};"
        : "+f"(d0), "+f"(d1), "+f"(d2), "+f"(d3)
        : "r"(a0), "r"(a1), "r"(a2), "r"(a3), "r"(b0), "r"(b1));
}

// ---------------------------------------------------------------------------
// Fused prologue: all weight transposes (+ tf32 rounding) + bias concat
// in ONE launch. Blocks 0..255: Wth; 256..511: Wph; 512..1535: Wg; 1536: bias.
// ---------------------------------------------------------------------------
__global__ void prep_all_kernel(const float* __restrict__ Wth,
                                const float* __restrict__ Wph,
                                const float* __restrict__ Wg,
                                const float* __restrict__ bth,
                                const float* __restrict__ bph,
                                float* __restrict__ wtp,
                                float* __restrict__ wg,
                                float* __restrict__ bias)
{
    __shared__ float tile[32][33];
    const int b = blockIdx.x;
    const int tx = threadIdx.x, ty = threadIdx.y;   // 32 x 8

    if (b >= 1536) {
        int i = ty * 32 + tx;          // 0..255
        bias[i] = bth[i];
        bias[i + 256] = bph[i];
        return;
    }

    const float* src;
    float* dst;
    int K, N, n0, k0;
    if (b < 256) {
        src = Wth; dst = wtp; K = 1024; N = 256;
        n0 = (b & 7) * 32; k0 = (b >> 3) * 32;
    } else if (b < 512) {
        int t = b - 256;
        src = Wph; dst = wtp + (size_t)256 * 1024; K = 1024; N = 256;
        n0 = (t & 7) * 32; k0 = (t >> 3) * 32;
    } else {
        int t = b - 512;
        src = Wg; dst = wg; K = 1024; N = 1024;
        n0 = (t & 31) * 32; k0 = (t >> 5) * 32;
    }
#pragma unroll
    for (int r = 0; r < 32; r += 8)
        tile[ty + r][tx] = src[(size_t)(k0 + ty + r) * N + n0 + tx];
    __syncthreads();
#pragma unroll
    for (int r = 0; r < 32; r += 8)
        dst[(size_t)(n0 + ty + r) * K + k0 + tx] = rna_tf32(tile[tx][ty + r]);
}

// ---------------------------------------------------------------------------
// tf32 mma.sync GEMM with ldmatrix fragments (R14/R15 configuration — best).
// C[M,N] = op(A[M,K] @ Bt[N,K]^T) (+bias) (relu) (rna_out). K compile-time.
// CTA 128x128, BK=32, 3-stage cp.async, 256 threads (8 warps 2x4,
// warp tile 64x32, 4x4 m16n8k8 per k-step), 2 CTAs/SM, unroll-3 chunk loop.
// RNAOUT=1 rounds outputs to tf32 (for g_tp, consumed raw by sim's MMA).
// ---------------------------------------------------------------------------
#define STAGE_BYTES 32768u                 // A 16KB + B 16KB
#define GEMM_SMEM   (3 * 32768)            // 98304 bytes -> 2 CTAs/SM

template <int RELU, int HASBIAS, int K, int RNAOUT>
__global__ void __launch_bounds__(256) gemm_tf32(
    const float* __restrict__ A, int lda,
    const float* __restrict__ Bt, int ldb,
    const float* __restrict__ bias,
    float* __restrict__ C, int ldc)
{
    extern __shared__ float sm[];
    const uint32_t smBase = smem_u32(sm);

    const int tid = threadIdx.x;
    const int bm = blockIdx.y * 128;
    const int bn = blockIdx.x * 128;

    const int wid  = tid >> 5;
    const int lane = tid & 31;
    const int g = lane >> 2;                // MMA groupID
    const int t = lane & 3;                 // MMA threadID_in_group
    const int warp_m = (wid & 1) * 64;
    const int warp_n = (wid >> 1) * 32;

    // ldmatrix per-lane row indices (within 128-row tile)
    const int aRow[4] = {
        warp_m + 0 * 16 + (lane & 7) + ((lane >> 3) & 1) * 8,
        warp_m + 1 * 16 + (lane & 7) + ((lane >> 3) & 1) * 8,
        warp_m + 2 * 16 + (lane & 7) + ((lane >> 3) & 1) * 8,
        warp_m + 3 * 16 + (lane & 7) + ((lane >> 3) & 1) * 8 };
    const int aCsel = lane >> 4;            // 0/1 -> k chunk lo/hi
    const int bRow[2] = {
        warp_n + (0 + ((lane >> 4) & 1)) * 8 + (lane & 7),
        warp_n + (2 + ((lane >> 4) & 1)) * 8 + (lane & 7) };
    const int bCsel = (lane >> 3) & 1;

    // stage one BK=32 chunk into buffer s (8 x cp.async 16B per thread)
    auto stage = [&](int kc, int s) {
        const int k0 = kc * 32;
        const uint32_t base = smBase + (uint32_t)s * STAGE_BYTES;
#pragma unroll
        for (int r = 0; r < 4; ++r) {
            int idx = tid + 256 * r;               // 0..1023
            int row = idx >> 3, c = idx & 7;
            uint32_t dst = base + (uint32_t)(row * 128 + ((c ^ (row & 7)) << 4));
            cp_async16(dst, A + (size_t)(bm + row) * lda + k0 + c * 4);
        }
#pragma unroll
        for (int r = 0; r < 4; ++r) {
            int idx = tid + 256 * r;
            int row = idx >> 3, c = idx & 7;
            uint32_t dst = base + 16384u + (uint32_t)(row * 128 + ((c ^ (row & 7)) << 4));
            cp_async16(dst, Bt + (size_t)(bn + row) * ldb + k0 + c * 4);
        }
    };

    float acc[4][4][4];
#pragma unroll
    for (int mt = 0; mt < 4; ++mt)
#pragma unroll
        for (int nt = 0; nt < 4; ++nt)
#pragma unroll
            for (int q = 0; q < 4; ++q) acc[mt][nt][q] = 0.f;

    constexpr int NC = K / 32;             // 32, compile-time
    stage(0, 0); CP_COMMIT();
    stage(1, 1); CP_COMMIT();

#pragma unroll 3
    for (int i = 0; i < NC; ++i) {
        CP_WAIT1();               // this thread's copies of chunk i done
        __syncthreads();          // all threads' copies visible; buf (i+2)%3 free
        if (i + 2 < NC) stage(i + 2, (i + 2) % 3);
        CP_COMMIT();

        const uint32_t sb = smBase + (uint32_t)(i % 3) * STAGE_BYTES;
#pragma unroll
        for (int ks = 0; ks < 4; ++ks) {
            uint32_t a[4][4];
#pragma unroll
            for (int mt = 0; mt < 4; ++mt) {
                const int row = aRow[mt];
                const int c = ks * 2 + aCsel;
                ldsm_x4(a[mt][0], a[mt][1], a[mt][2], a[mt][3],
                        sb + (uint32_t)(row * 128 + ((c ^ (row & 7)) << 4)));
            }
            uint32_t b[4][2];
#pragma unroll
            for (int p = 0; p < 2; ++p) {
                const int row = bRow[p];
                const int c = ks * 2 + bCsel;
                ldsm_x4(b[2 * p][0], b[2 * p][1], b[2 * p + 1][0], b[2 * p + 1][1],
                        sb + 16384u + (uint32_t)(row * 128 + ((c ^ (row & 7)) << 4)));
            }
#pragma unroll
            for (int mt = 0; mt < 4; ++mt)
#pragma unroll
                for (int nt = 0; nt < 4; ++nt)
                    mma_tf32(acc[mt][nt][0], acc[mt][nt][1],
                             acc[mt][nt][2], acc[mt][nt][3],
                             a[mt][0], a[mt][1], a[mt][2], a[mt][3],
                             b[nt][0], b[nt][1]);
        }
    }

    // Epilogue: c0,c1 -> (row, col..col+1); c2,c3 -> (row+8, col..col+1)
#pragma unroll
    for (int mt = 0; mt < 4; ++mt) {
        const int row = bm + warp_m + mt * 16 + g;
#pragma unroll
        for (int nt = 0; nt < 4; ++nt) {
            const int col = bn + warp_n + nt * 8 + 2 * t;
            float v0 = acc[mt][nt][0], v1 = acc[mt][nt][1];
            float v2 = acc[mt][nt][2], v3 = acc[mt][nt][3];
            if (HASBIAS) {
                float b0 = bias[col], b1 = bias[col + 1];
                v0 += b0; v1 += b1; v2 += b0; v3 += b1;
            }
            if (RELU) {
                v0 = fmaxf(v0, 0.f); v1 = fmaxf(v1, 0.f);
                v2 = fmaxf(v2, 0.f); v3 = fmaxf(v3, 0.f);
            }
            if (RNAOUT) {
                v0 = rna_tf32(v0); v1 = rna_tf32(v1);
                v2 = rna_tf32(v2); v3 = rna_tf32(v3);
            }
            *(float2*)(C + (size_t)row * ldc + col) = make_float2(v0, v1);
            *(float2*)(C + (size_t)(row + 8) * ldc + col) = make_float2(v2, v3);
        }
    }
}

// ---------------------------------------------------------------------------
// sim_softmax with tensor-core phase 1; staging via cp.async (g_tp is
// pre-rounded to tf32 by gemm1's RNAOUT epilogue -> raw copy is exact).
// One CTA per batch, 256 threads (8 warps, warp tile 32x16, K=256).
// sTP [128][260] ([row][k], pad 4 -> fragment banks 4g+t conflict-free).
// Softmax/mask/rel-write in exact fp32 (unchanged numerics).
// ---------------------------------------------------------------------------
#define SIM_TP    0                        // [128][260] floats (th rows 0..63, ph 64..127)
#define SIM_SS    (128 * 260)              // [64][68]
#define SIM_CX    (SIM_SS + 64 * 68)
#define SIM_CY    (SIM_CX + 64)
#define SIM_SMEM  ((SIM_CY + 64) * 4)      // 151,040 bytes

__global__ void __launch_bounds__(256) sim_softmax_kernel(
    const float* __restrict__ boxes, float* __restrict__ rel)
{
    extern __shared__ float smA[];
    float* sTP = smA + SIM_TP;      // theta rows 0..63, phi rows 64..127, stride 260
    float* sS  = smA + SIM_SS;      // [64][68]
    float* cx  = smA + SIM_CX;
    float* cy  = smA + SIM_CY;
    const uint32_t sTPa = smem_u32(sTP);

    const int b = blockIdx.x;
    const int tid = threadIdx.x;

    if (tid < 64) {
        const float* bb = boxes + ((size_t)b * 64 + tid) * 4;
        cx[tid] = (bb[0] + bb[2]) * 0.5f;
        cy[tid] = (bb[1] + bb[3]) * 0.5f;
    }

    // Stage theta|phi via cp.async (already tf32-rounded in g_tp).
    const float4* src4 = (const float4*)(g_tp + (size_t)b * 64 * 512);
#pragma unroll
    for (int r = 0; r < 32; ++r) {
        int i = tid + 256 * r;         // 0..8191 float4s
        int rr = i >> 7;               // batch row 0..63
        int c4 = i & 127;              // 0..63 theta, 64..127 phi
        int row = (c4 < 64) ? rr : (64 + rr);
        int k4  = (c4 & 63);
        cp_async16(sTPa + (uint32_t)(row * 260 + k4 * 4) * 4, src4 + rr * 128 + c4);
    }
    CP_COMMIT();
    CP_WAIT0();
    __syncthreads();

    // MMA: sim[64,64] = theta @ phi^T. 8 warps: warp_m=(w&1)*32, warp_n=(w>>1)*16.
    const int wid  = tid >> 5;
    const int lane = tid & 31;
    const int g = lane >> 2;
    const int t = lane & 3;
    const int warp_m = (wid & 1) * 32;
    const int warp_n = (wid >> 1) * 16;

    float acc[2][2][4];
#pragma unroll
    for (int mt = 0; mt < 2; ++mt)
#pragma unroll
        for (int nt = 0; nt < 2; ++nt)
#pragma unroll
            for (int q = 0; q < 4; ++q) acc[mt][nt][q] = 0.f;

    const float* sTH = sTP;             // theta rows
    const float* sPH = sTP + 64 * 260;  // phi rows

#pragma unroll 4
    for (int ks = 0; ks < 32; ++ks) {
        const int k0 = ks * 8;
        uint32_t a[2][4];
#pragma unroll
        for (int mt = 0; mt < 2; ++mt) {
            const int r0 = warp_m + mt * 16 + g;
            a[mt][0] = __float_as_uint(sTH[r0 * 260 + k0 + t]);
            a[mt][1] = __float_as_uint(sTH[(r0 + 8) * 260 + k0 + t]);
            a[mt][2] = __float_as_uint(sTH[r0 * 260 + k0 + 4 + t]);
            a[mt][3] = __float_as_uint(sTH[(r0 + 8) * 260 + k0 + 4 + t]);
        }
        uint32_t bf[2][2];
#pragma unroll
        for (int nt = 0; nt < 2; ++nt) {
            const int n = warp_n + nt * 8 + g;
            bf[nt][0] = __float_as_uint(sPH[n * 260 + k0 + t]);
            bf[nt][1] = __float_as_uint(sPH[n * 260 + k0 + 4 + t]);
        }
#pragma unroll
        for (int mt = 0; mt < 2; ++mt)
#pragma unroll
            for (int nt = 0; nt < 2; ++nt)
                mma_tf32(acc[mt][nt][0], acc[mt][nt][1],
                         acc[mt][nt][2], acc[mt][nt][3],
                         a[mt][0], a[mt][1], a[mt][2], a[mt][3],
                         bf[nt][0], bf[nt][1]);
    }

    // write sim/16 into sS
#pragma unroll
    for (int mt = 0; mt < 2; ++mt) {
        const int row = warp_m + mt * 16 + g;
#pragma unroll
        for (int nt = 0; nt < 2; ++nt) {
            const int col = warp_n + nt * 8 + 2 * t;
            sS[row * 68 + col]     = acc[mt][nt][0] * 0.0625f;
            sS[row * 68 + col + 1] = acc[mt][nt][1] * 0.0625f;
            sS[(row + 8) * 68 + col]     = acc[mt][nt][2] * 0.0625f;
            sS[(row + 8) * 68 + col + 1] = acc[mt][nt][3] * 0.0625f;
        }
    }
    __syncthreads();

    // mask + softmax: warp w handles rows 8w..8w+7; lanes cover m (2 each)
    {
        const int w = tid >> 5;
        const int ln = tid & 31;
        const float thr2 = (0.2f * 157.0f) * (0.2f * 157.0f);
#pragma unroll
        for (int r = 0; r < 8; ++r) {
            const int n = w * 8 + r;
            const float cxn = cx[n], cyn = cy[n];
            float dx0 = cxn - cx[ln], dy0 = cyn - cy[ln];
            float dx1 = cxn - cx[ln + 32], dy1 = cyn - cy[ln + 32];
            float v0 = (dx0 * dx0 + dy0 * dy0 > thr2) ? -INFINITY : sS[n * 68 + ln];
            float v1 = (dx1 * dx1 + dy1 * dy1 > thr2) ? -INFINITY : sS[n * 68 + ln + 32];
            float mx = fmaxf(v0, v1);
#pragma unroll
            for (int o = 16; o; o >>= 1)
                mx = fmaxf(mx, __shfl_xor_sync(0xFFFFFFFFu, mx, o));
            float e0 = expf(v0 - mx);
            float e1 = expf(v1 - mx);
            float s = e0 + e1;
#pragma unroll
            for (int o = 16; o; o >>= 1)
                s += __shfl_xor_sync(0xFFFFFFFFu, s, o);
            const float inv = 1.f / s;
            sS[n * 68 + ln] = e0 * inv;
            sS[n * 68 + ln + 32] = e1 * inv;
        }
    }
    __syncthreads();

    float* ro = rel + (size_t)b * 4096;
    for (int i = tid; i < 4096; i += 256)
        ro[i] = sS[(i >> 6) * 68 + (i & 63)];
}

// ---------------------------------------------------------------------------
// agg = relation[64,64] @ feats[64,1024] via tf32 mma.sync (R15 — best).
// Staging via cp.async (raw); RNA at fragment LDS reads (bit-identical).
// CTA = (batch, 256-col chunk), 256 threads = 8 warps, warp tile 64x32, K=64.
// ---------------------------------------------------------------------------
#define AGG_SMEM ((64 * 264 + 64 * 68) * 4)   // 84992

__global__ void __launch_bounds__(256) agg_kernel(
    const float* __restrict__ feats, const float* __restrict__ rel,
    float* __restrict__ agg)
{
    extern __shared__ float smA[];
    float* sfeats = smA;                 // [64][264]  ([m][f]) raw fp32
    float* srel   = smA + 64 * 264;      // [64][68]   ([n][m]) raw fp32
    const uint32_t sfA = smem_u32(sfeats);
    const uint32_t srA = smem_u32(srel);

    const int b = blockIdx.x;
    const int fchunk = blockIdx.y * 256;
    const int tid = threadIdx.x;

    // stage feats chunk via cp.async (raw)
    const float* fsrc = feats + (size_t)b * 64 * 1024 + fchunk;
#pragma unroll
    for (int r = 0; r < 16; ++r) {
        int idx = tid + 256 * r;        // 0..4095 float4s
        int m = idx >> 6, c4 = idx & 63;
        cp_async16(sfA + (uint32_t)(m * 264 + c4 * 4) * 4,
                   fsrc + (size_t)m * 1024 + c4 * 4);
    }
    // stage rel via cp.async (raw)
    const float* rsrc = rel + (size_t)b * 4096;
#pragma unroll
    for (int r = 0; r < 4; ++r) {
        int idx = tid + 256 * r;        // 0..1023 float4s
        int n = idx >> 4, c4 = idx & 15;
        cp_async16(srA + (uint32_t)(n * 68 + c4 * 4) * 4,
                   rsrc + idx * 4);
    }
    CP_COMMIT();
    CP_WAIT0();
    __syncthreads();

    const int wid  = tid >> 5;
    const int lane = tid & 31;
    const int g = lane >> 2;
    const int t = lane & 3;
    const int warp_n = wid * 32;         // f-offset within 256 chunk

    float acc[4][4][4];
#pragma unroll
    for (int mt = 0; mt < 4; ++mt)
#pragma unroll
        for (int nt = 0; nt < 4; ++nt)
#pragma unroll
            for (int q = 0; q < 4; ++q) acc[mt][nt][q] = 0.f;

#pragma unroll
    for (int ks = 0; ks < 8; ++ks) {
        const int k0 = ks * 8;
        uint32_t a[4][4];
#pragma unroll
        for (int mt = 0; mt < 4; ++mt) {
            a[mt][0] = rna_tf32_u(srel[(mt * 16 + g) * 68 + k0 + t]);
            a[mt][1] = rna_tf32_u(srel[(mt * 16 + 8 + g) * 68 + k0 + t]);
            a[mt][2] = rna_tf32_u(srel[(mt * 16 + g) * 68 + k0 + 4 + t]);
            a[mt][3] = rna_tf32_u(srel[(mt * 16 + 8 + g) * 68 + k0 + 4 + t]);
        }
        uint32_t bf[4][2];
#pragma unroll
        for (int nt = 0; nt < 4; ++nt) {
            bf[nt][0] = rna_tf32_u(sfeats[(k0 + t) * 264 + warp_n + nt * 8 + g]);
            bf[nt][1] = rna_tf32_u(sfeats[(k0 + 4 + t) * 264 + warp_n + nt * 8 + g]);
        }
#pragma unroll
        for (int mt = 0; mt < 4; ++mt)
#pragma unroll
            for (int nt = 0; nt < 4; ++nt)
                mma_tf32(acc[mt][nt][0], acc[mt][nt][1],
                         acc[mt][nt][2], acc[mt][nt][3],
                         a[mt][0], a[mt][1], a[mt][2], a[mt][3],
                         bf[nt][0], bf[nt][1]);
    }

    // Epilogue: RNA-round for gemm2 consumption
#pragma unroll
    for (int mt = 0; mt < 4; ++mt) {
        const size_t row0 = (size_t)b * 64 + mt * 16 + g;
#pragma unroll
        for (int nt = 0; nt < 4; ++nt) {
            const int col = fchunk + warp_n + nt * 8 + 2 * t;
            float2 p0 = make_float2(rna_tf32(acc[mt][nt][0]), rna_tf32(acc[mt][nt][1]));
            float2 p1 = make_float2(rna_tf32(acc[mt][nt][2]), rna_tf32(acc[mt][nt][3]));
            *(float2*)(agg + row0 * 1024 + col) = p0;
            *(float2*)(agg + (row0 + 8) * 1024 + col) = p1;
        }
    }
}

// ---------------------------------------------------------------------------
extern "C" void kernel_launch(void* const* d_in, const int* in_sizes, int n_in,
                              void* d_out, int out_size)
{
    const float* feats = (const float*)d_in[0];
    const float* boxes = (const float*)d_in[1];
    const float* Wth   = (const float*)d_in[2];
    const float* bth   = (const float*)d_in[3];
    const float* Wph   = (const float*)d_in[4];
    const float* bph   = (const float*)d_in[5];
    const float* Wg    = (const float*)d_in[6];
    float* out = (float*)d_out;

    float *tp, *agg, *relScratch, *wtp, *wg, *bias;
    cudaGetSymbolAddress((void**)&tp, g_tp);
    cudaGetSymbolAddress((void**)&agg, g_agg);
    cudaGetSymbolAddress((void**)&relScratch, g_rel);
    cudaGetSymbolAddress((void**)&wtp, g_wtp);
    cudaGetSymbolAddress((void**)&wg, g_wg);
    cudaGetSymbolAddress((void**)&bias, g_bias);

    cudaFuncSetAttribute(gemm_tf32<0, 1, 1024, 1>,
                         cudaFuncAttributeMaxDynamicSharedMemorySize, GEMM_SMEM);
    cudaFuncSetAttribute(gemm_tf32<1, 0, 1024, 0>,
                         cudaFuncAttributeMaxDynamicSharedMemorySize, GEMM_SMEM);
    cudaFuncSetAttribute(sim_softmax_kernel,
                         cudaFuncAttributeMaxDynamicSharedMemorySize, SIM_SMEM);
    cudaFuncSetAttribute(agg_kernel,
                         cudaFuncAttributeMaxDynamicSharedMemorySize, AGG_SMEM);

    float* rel = ((size_t)out_size >= OUT_ELEMS + REL_ELEMS)
                     ? out + OUT_ELEMS
                     : relScratch;

    // 5 launches; agg sits in the ncu capture slot (#4).
    prep_all_kernel<<<1537, dim3(32, 8)>>>(Wth, Wph, Wg, bth, bph, wtp, wg, bias); // 1
    gemm_tf32<0, 1, 1024, 1><<<dim3(4, 256), 256, GEMM_SMEM>>>(                    // 2
        feats, NFG, wtp, NFG, bias, tp, 512);
    sim_softmax_kernel<<<BB, 256, SIM_SMEM>>>(boxes, rel);                         // 3
    agg_kernel<<<dim3(BB, 4), 256, AGG_SMEM>>>(feats, rel, agg);                   // 4
    gemm_tf32<1, 0, 1024, 0><<<dim3(8, 256), 256, GEMM_SMEM>>>(                    // 5
        agg, NFG, wg, NFG, nullptr, out, NFG);
}